// round 6
// baseline (speedup 1.0000x reference)
#include <cuda_runtime.h>
#include <cstdint>

#define B_   8
#define HW_  16384
#define PB   (256LL*256LL)

// ---------------- scratch ----------------
__device__ float g_Hp[B_*256*256];
__device__ float g_Mp[B_*256*256];
__device__ float g_Yh[B_*3*256*256];          // Qp,Kp,Vp per batch
__device__ float g_Ym[B_*2*256*256];          // Kmp,Vmp
__device__ float g_S [2*B_*256*256];          // scores/attn (h then m)
__device__ float g_ZT[B_*512*256];            // Zh rows 0..255, Zm 256..511 (d-major)
__device__ float g_G [B_*768*256];            // Wzz @ Zcat on 16x16 grid
__device__ float g_Wzz[768*512];
__device__ float g_bf[768];

// ---------------- pooling ----------------
__global__ void pool_kernel(const float* __restrict__ h, const float* __restrict__ m)
{
    int gwarp = (blockIdx.x * blockDim.x + threadIdx.x) >> 5;
    int lane  = threadIdx.x & 31;
    const float* src = blockIdx.y ? m : h;
    float* dst       = blockIdx.y ? g_Mp : g_Hp;
    float2 v = *(const float2*)(src + (size_t)gwarp * 64 + lane * 2);
    float s = v.x + v.y;
    #pragma unroll
    for (int o = 16; o; o >>= 1) s += __shfl_xor_sync(0xffffffffu, s, o);
    if (lane == 0) dst[gwarp] = s * (1.0f / 64.0f);
}

// ---------------- batched-pointer fp32 GEMM (64x64 tile) ----------------
struct GArgs {
    const float* A[40];
    const float* B[40];
    float*       C[40];
    const float* bias[40];
};

template<bool TA, bool TB, bool BIAS>
__global__ void __launch_bounds__(256) gemm_b(
    GArgs ga, int lda, int ldb, int ldc, int K)
{
    __shared__ float As[16][68];   // [k][m]
    __shared__ float Bs[16][68];   // [k][n]
    int tid = threadIdx.x;
    int z = blockIdx.z;
    const float* Ab = ga.A[z];
    const float* Bb = ga.B[z];
    float* Cb       = ga.C[z];
    int m0 = blockIdx.y * 64, n0 = blockIdx.x * 64;
    float acc[4][4] = {};
    int tr = tid >> 4, tc = tid & 15;

    for (int k0 = 0; k0 < K; k0 += 16) {
        if (!TA) {
            int mm = tid >> 2, kq = (tid & 3) * 4;
            float4 v = *(const float4*)&Ab[(size_t)(m0+mm)*lda + k0 + kq];
            As[kq+0][mm]=v.x; As[kq+1][mm]=v.y; As[kq+2][mm]=v.z; As[kq+3][mm]=v.w;
        } else {
            int kk = tid >> 4, mq = (tid & 15) * 4;
            float4 v = *(const float4*)&Ab[(size_t)(k0+kk)*lda + m0 + mq];
            As[kk][mq+0]=v.x; As[kk][mq+1]=v.y; As[kk][mq+2]=v.z; As[kk][mq+3]=v.w;
        }
        if (!TB) {
            int kk = tid >> 4, nq = (tid & 15) * 4;
            float4 v = *(const float4*)&Bb[(size_t)(k0+kk)*ldb + n0 + nq];
            Bs[kk][nq+0]=v.x; Bs[kk][nq+1]=v.y; Bs[kk][nq+2]=v.z; Bs[kk][nq+3]=v.w;
        } else {
            int nn = tid >> 2, kq = (tid & 3) * 4;
            float4 v = *(const float4*)&Bb[(size_t)(n0+nn)*ldb + k0 + kq];
            Bs[kq+0][nn]=v.x; Bs[kq+1][nn]=v.y; Bs[kq+2][nn]=v.z; Bs[kq+3][nn]=v.w;
        }
        __syncthreads();
        #pragma unroll
        for (int k = 0; k < 16; k++) {
            float4 a4 = *(const float4*)&As[k][tr*4];
            float4 b4 = *(const float4*)&Bs[k][tc*4];
            float a[4] = {a4.x,a4.y,a4.z,a4.w};
            float b[4] = {b4.x,b4.y,b4.z,b4.w};
            #pragma unroll
            for (int i = 0; i < 4; i++)
                #pragma unroll
                for (int j = 0; j < 4; j++) acc[i][j] += a[i] * b[j];
        }
        __syncthreads();
    }
    #pragma unroll
    for (int i = 0; i < 4; i++) {
        float bv = BIAS ? ga.bias[z][m0 + tr*4 + i] : 0.0f;
        float4 v = { acc[i][0]+bv, acc[i][1]+bv, acc[i][2]+bv, acc[i][3]+bv };
        *(float4*)&Cb[(size_t)(m0+tr*4+i)*ldc + n0 + tc*4] = v;
    }
}

// ---------------- softmax over rows of 256 ----------------
__global__ void softmax_kernel()
{
    float* row = g_S + (size_t)blockIdx.x * 256;
    int tid = threadIdx.x;
    float v = row[tid];
    __shared__ float red[8];
    float mx = v;
    #pragma unroll
    for (int o = 16; o; o >>= 1) mx = fmaxf(mx, __shfl_xor_sync(0xffffffffu, mx, o));
    if ((tid & 31) == 0) red[tid >> 5] = mx;
    __syncthreads();
    float bmax = red[0];
    #pragma unroll
    for (int i = 1; i < 8; i++) bmax = fmaxf(bmax, red[i]);
    float e = expf(v - bmax);
    float s = e;
    #pragma unroll
    for (int o = 16; o; o >>= 1) s += __shfl_xor_sync(0xffffffffu, s, o);
    __syncthreads();
    if ((tid & 31) == 0) red[tid >> 5] = s;
    __syncthreads();
    float bsum = red[0];
    #pragma unroll
    for (int i = 1; i < 8; i++) bsum += red[i];
    row[tid] = e / bsum;
}

// ---------------- bfold[r] = bm[r] + sum_{o<512} wm[r,o]*bz[o] ----------
__global__ void bfold_kernel(const float* __restrict__ wm,
                             const float* __restrict__ bz,
                             const float* __restrict__ bm)
{
    int r = blockIdx.x * blockDim.x + threadIdx.x;
    if (r < 768) {
        float s = bm[r];
        for (int o = 0; o < 512; o++) s += wm[(size_t)r*768 + o] * bz[o];
        g_bf[r] = s;
    }
}

// ---------------- fused big GEMM + bilinear G + gating -------------------
// Block: 64 o-channels x 128 pixels (one image row y). Computes mo/mg/mi
// (3 wm slabs, M=192 rows) over K=256, then gates and writes new_h/new_m.
__device__ __forceinline__ uint32_t f2tf(float f) {
    uint32_t u; asm("cvt.rna.tf32.f32 %0, %1;" : "=r"(u) : "f"(f)); return u;
}

__global__ void __launch_bounds__(256) fused_gemm_gate(
    const float* __restrict__ wm,     // [768,768]; X-part cols 512..767
    const float* __restrict__ h,
    const float* __restrict__ m_in,
    float* __restrict__ out)
{
    __shared__ uint32_t As[192 * 36];   // tf32, row-major [r][k], pad 36
    __shared__ uint32_t Bs[32 * 136];   // tf32, [k][n], pad 136
    int tid = threadIdx.x;
    int y  = blockIdx.x;                // image row 0..127
    int m0 = blockIdx.y * 64;           // o base
    int b  = blockIdx.z;
    int lane = tid & 31, wid = tid >> 5;
    int wmi = wid >> 1;                 // 0..3 : 16 o's each
    int wni = wid & 1;                  // 0..1 : 64 px each
    int g = lane >> 2, tg = lane & 3;

    const float* Xb = h + (size_t)b * 256 * HW_ + (size_t)y * 128;

    float acc[3][8][4];
    #pragma unroll
    for (int s = 0; s < 3; s++)
        #pragma unroll
        for (int n = 0; n < 8; n++)
            #pragma unroll
            for (int c = 0; c < 4; c++) acc[s][n][c] = 0.0f;

    // A: 192 rows x 32k = 1536 float4; 6/thread. r=idx>>3, kq=(idx&7)*4
    // B: 32 k x 128 = 1024 float4; 4/thread. kk=idx>>5, nf=idx&31
    float4 pa[6], pb[4];
    #pragma unroll
    for (int i = 0; i < 6; i++) {
        int idx = tid + 256*i;
        int r = idx >> 3, kq = (idx & 7) * 4;
        int grow = (r >> 6) * 256 + m0 + (r & 63);
        pa[i] = *(const float4*)&wm[(size_t)grow*768 + 512 + kq];
    }
    #pragma unroll
    for (int i = 0; i < 4; i++) {
        int idx = tid + 256*i;
        int kk = idx >> 5, nf = idx & 31;
        pb[i] = *(const float4*)&Xb[(size_t)kk*HW_ + nf*4];
    }

    for (int kt = 0; kt < 8; kt++) {
        #pragma unroll
        for (int i = 0; i < 6; i++) {
            int idx = tid + 256*i;
            int r = idx >> 3, kq = (idx & 7) * 4;
            uint4 t = { f2tf(pa[i].x), f2tf(pa[i].y), f2tf(pa[i].z), f2tf(pa[i].w) };
            *(uint4*)&As[r*36 + kq] = t;
        }
        #pragma unroll
        for (int i = 0; i < 4; i++) {
            int idx = tid + 256*i;
            int kk = idx >> 5, nf = idx & 31;
            uint4 t = { f2tf(pb[i].x), f2tf(pb[i].y), f2tf(pb[i].z), f2tf(pb[i].w) };
            *(uint4*)&Bs[kk*136 + nf*4] = t;
        }
        __syncthreads();
        if (kt < 7) {
            int k0 = (kt + 1) * 32;
            #pragma unroll
            for (int i = 0; i < 6; i++) {
                int idx = tid + 256*i;
                int r = idx >> 3, kq = (idx & 7) * 4;
                int grow = (r >> 6) * 256 + m0 + (r & 63);
                pa[i] = *(const float4*)&wm[(size_t)grow*768 + 512 + k0 + kq];
            }
            #pragma unroll
            for (int i = 0; i < 4; i++) {
                int idx = tid + 256*i;
                int kk = idx >> 5, nf = idx & 31;
                pb[i] = *(const float4*)&Xb[(size_t)(k0+kk)*HW_ + nf*4];
            }
        }
        #pragma unroll
        for (int ks = 0; ks < 4; ks++) {
            int kk = ks * 8;
            uint32_t bfr[8][2];
            #pragma unroll
            for (int nt = 0; nt < 8; nt++) {
                int n = wni*64 + nt*8;
                bfr[nt][0] = Bs[(kk+tg  )*136 + n + g];
                bfr[nt][1] = Bs[(kk+tg+4)*136 + n + g];
            }
            #pragma unroll
            for (int s = 0; s < 3; s++) {
                int rb = s*64 + wmi*16;
                uint32_t a0 = As[(rb + g    )*36 + kk + tg    ];
                uint32_t a1 = As[(rb + 8 + g)*36 + kk + tg    ];
                uint32_t a2 = As[(rb + g    )*36 + kk + tg + 4];
                uint32_t a3 = As[(rb + 8 + g)*36 + kk + tg + 4];
                #pragma unroll
                for (int nt = 0; nt < 8; nt++)
                    asm volatile(
                        "mma.sync.aligned.m16n8k8.row.col.f32.tf32.tf32.f32 "
                        "{%0,%1,%2,%3},{%4,%5,%6,%7},{%8,%9},{%0,%1,%2,%3};\n"
                        : "+f"(acc[s][nt][0]), "+f"(acc[s][nt][1]),
                          "+f"(acc[s][nt][2]), "+f"(acc[s][nt][3])
                        : "r"(a0), "r"(a1), "r"(a2), "r"(a3),
                          "r"(bfr[nt][0]), "r"(bfr[nt][1]));
            }
        }
        __syncthreads();
    }

    // ---- epilogue: gy = y-interpolated G rows, then x-interp + gating ----
    float* gy = (float*)As;   // [192][16], reuse As
    float sy = (y + 0.5f) * 0.125f - 0.5f; if (sy < 0.0f) sy = 0.0f;
    int y0 = (int)sy; float fy = sy - (float)y0; int y1 = min(y0 + 1, 15);
    #pragma unroll
    for (int i = 0; i < 12; i++) {
        int idx = tid + 256*i;
        int r = idx >> 4, px = idx & 15;
        int grow = (r >> 6) * 256 + m0 + (r & 63);
        const float* Gb = g_G + ((size_t)b*768 + grow) * 256;
        gy[r*16 + px] = (1.0f - fy) * Gb[y0*16 + px] + fy * Gb[y1*16 + px];
    }
    __syncthreads();

    #pragma unroll
    for (int rr = 0; rr < 2; rr++) {
        int o_loc  = wmi*16 + g + rr*8;
        int o_glob = m0 + o_loc;
        float bv0 = g_bf[o_glob];
        float bv1 = g_bf[256 + o_glob];
        float bv2 = g_bf[512 + o_glob];
        const float* mrow = m_in + ((size_t)b*256 + o_glob)*HW_ + (size_t)y*128;
        float* hrow = out + ((size_t)b*256 + o_glob)*HW_ + (size_t)y*128;
        float* mrow_out = hrow + (size_t)B_*256*HW_;
        #pragma unroll
        for (int nt = 0; nt < 8; nt++) {
            int x = wni*64 + nt*8 + tg*2;
            float2 mv = *(const float2*)&mrow[x];
            float nh[2], nm[2];
            #pragma unroll
            for (int px = 0; px < 2; px++) {
                int xx = x + px;
                float sx = (xx + 0.5f) * 0.125f - 0.5f; if (sx < 0.0f) sx = 0.0f;
                int x0 = (int)sx; float fx = sx - (float)x0; int x1 = min(x0 + 1, 15);
                float g0 = (1.0f-fx)*gy[(0*64+o_loc)*16 + x0] + fx*gy[(0*64+o_loc)*16 + x1];
                float g1 = (1.0f-fx)*gy[(1*64+o_loc)*16 + x0] + fx*gy[(1*64+o_loc)*16 + x1];
                float g2 = (1.0f-fx)*gy[(2*64+o_loc)*16 + x0] + fx*gy[(2*64+o_loc)*16 + x1];
                int c = rr*2 + px;
                float mo = acc[0][nt][c] + bv0 + g0;
                float mg = acc[1][nt][c] + bv1 + g1;
                float mi = acc[2][nt][c] + bv2 + g2;
                float mval = px ? mv.y : mv.x;
                float gi = 1.0f / (1.0f + expf(-mi));
                float nmv = (1.0f - gi) * mval + gi * tanhf(mg);
                nm[px] = nmv;
                nh[px] = nmv / (1.0f + expf(-mo));
            }
            *(float2*)&hrow[x]     = make_float2(nh[0], nh[1]);
            *(float2*)&mrow_out[x] = make_float2(nm[0], nm[1]);
        }
    }
}

// ---------------- launcher ----------------
extern "C" void kernel_launch(void* const* d_in, const int* in_sizes, int n_in,
                              void* d_out, int out_size)
{
    const float* h   = (const float*)d_in[0];
    const float* m   = (const float*)d_in[1];
    const float* wq  = (const float*)d_in[2];
    const float* bq  = (const float*)d_in[3];
    const float* wk  = (const float*)d_in[4];
    const float* bk  = (const float*)d_in[5];
    const float* wv  = (const float*)d_in[6];
    const float* bv  = (const float*)d_in[7];
    const float* wkm = (const float*)d_in[8];
    const float* bkm = (const float*)d_in[9];
    const float* wvm = (const float*)d_in[10];
    const float* bvm = (const float*)d_in[11];
    const float* wz  = (const float*)d_in[12];
    const float* bz  = (const float*)d_in[13];
    const float* wm  = (const float*)d_in[14];
    const float* bm  = (const float*)d_in[15];
    float* out = (float*)d_out;

    float *Hp, *Mp, *Yh, *Ym, *S, *ZT, *G, *Wzz;
    cudaGetSymbolAddress((void**)&Hp,  g_Hp);
    cudaGetSymbolAddress((void**)&Mp,  g_Mp);
    cudaGetSymbolAddress((void**)&Yh,  g_Yh);
    cudaGetSymbolAddress((void**)&Ym,  g_Ym);
    cudaGetSymbolAddress((void**)&S,   g_S);
    cudaGetSymbolAddress((void**)&ZT,  g_ZT);
    cudaGetSymbolAddress((void**)&G,   g_G);
    cudaGetSymbolAddress((void**)&Wzz, g_Wzz);

    // 1) pooling
    pool_kernel<<<dim3(65536, 2), 256>>>(h, m);

    // 2) folded weights / bias (independent of pooling)
    {
        GArgs ga = {};
        ga.A[0] = wm; ga.B[0] = wz; ga.C[0] = Wzz;
        gemm_b<false,false,false><<<dim3(8,12,1), 256>>>(ga, 768, 512, 512, 512);
    }
    bfold_kernel<<<3, 256>>>(wm, bz, bm);

    // 3) all five projections in one launch (z = slab*8 + batch)
    {
        GArgs ga = {};
        const float* W5[5] = { wq, wk, wv, wkm, wvm };
        const float* b5[5] = { bq, bk, bv, bkm, bvm };
        for (int s = 0; s < 5; s++)
            for (int bt = 0; bt < 8; bt++) {
                int z = s*8 + bt;
                ga.A[z] = W5[s];
                ga.B[z] = (s < 3 ? Hp : Mp) + bt*PB;
                ga.C[z] = (s < 3) ? Yh + bt*3*PB + s*PB
                                  : Ym + bt*2*PB + (s-3)*PB;
                ga.bias[z] = b5[s];
            }
        gemm_b<false,false,true><<<dim3(4,4,40), 256>>>(ga, 256, 256, 256, 256);
    }

    // 4) scores (h and m) in one launch: S[z][p,q] = Q^T K
    {
        GArgs ga = {};
        for (int z = 0; z < 16; z++) {
            int bt = z & 7;
            ga.A[z] = Yh + bt*3*PB;                                   // Qp
            ga.B[z] = (z < 8) ? Yh + bt*3*PB + PB : Ym + bt*2*PB;     // Kp / Kmp
            ga.C[z] = S + (long long)z*PB;
        }
        gemm_b<true,false,false><<<dim3(4,4,16), 256>>>(ga, 256, 256, 256, 256);
    }

    // 5) softmax
    softmax_kernel<<<4096, 256>>>();

    // 6) ZT[d,p] = V @ A^T (h and m) in one launch
    {
        GArgs ga = {};
        for (int z = 0; z < 16; z++) {
            int bt = z & 7;
            ga.A[z] = (z < 8) ? Yh + bt*3*PB + 2*PB : Ym + bt*2*PB + PB;
            ga.B[z] = S + (long long)z*PB;
            ga.C[z] = ZT + bt*2*PB + ((z < 8) ? 0 : PB);
        }
        gemm_b<false,true,false><<<dim3(4,4,16), 256>>>(ga, 256, 256, 256, 256);
    }

    // 7) G = Wzz @ ZTcat
    {
        GArgs ga = {};
        for (int bt = 0; bt < 8; bt++) {
            ga.A[bt] = Wzz;
            ga.B[bt] = ZT + bt*2*PB;
            ga.C[bt] = G + (long long)bt*768*256;
        }
        gemm_b<false,false,false><<<dim3(4,12,8), 256>>>(ga, 512, 256, 256, 512);
    }

    // 8) fused big GEMM + upsample + gating -> outputs
    fused_gemm_gate<<<dim3(128, 4, 8), 256>>>(wm, h, m, out);
}

// round 8
// speedup vs baseline: 1.1449x; 1.1449x over previous
#include <cuda_runtime.h>
#include <cuda_fp16.h>
#include <cstdint>

#define B_   8
#define HW_  16384
#define PB   (256LL*256LL)

// ---------------- scratch ----------------
__device__ float g_Hp[B_*256*256];
__device__ float g_Mp[B_*256*256];
__device__ float g_Yh[B_*3*256*256];          // Qp,Kp,Vp per batch
__device__ float g_Ym[B_*2*256*256];          // Kmp,Vmp
__device__ float g_S [2*B_*256*256];          // scores/attn (h then m)
__device__ float g_ZT[B_*512*256];            // Zh rows 0..255, Zm 256..511 (d-major)
__device__ float g_G [B_*768*256];            // Wzz @ Zcat on 16x16 grid
__device__ float g_Wzz[768*512];
__device__ float g_bf[768];
__device__ __half g_h16[(size_t)B_*256*HW_];  // fp16 copy of h (64 MiB)
__device__ __half g_w16[768*256];             // fp16 copy of wm[:,512:768]

// ---------------- pooling (+ fp16 emit of h) ----------------
__global__ void pool_kernel(const float* __restrict__ h, const float* __restrict__ m)
{
    int gwarp = (blockIdx.x * blockDim.x + threadIdx.x) >> 5;
    int lane  = threadIdx.x & 31;
    const float* src = blockIdx.y ? m : h;
    float* dst       = blockIdx.y ? g_Mp : g_Hp;
    float2 v = *(const float2*)(src + (size_t)gwarp * 64 + lane * 2);
    if (blockIdx.y == 0)
        *(__half2*)(g_h16 + (size_t)gwarp * 64 + lane * 2) = __floats2half2_rn(v.x, v.y);
    float s = v.x + v.y;
    #pragma unroll
    for (int o = 16; o; o >>= 1) s += __shfl_xor_sync(0xffffffffu, s, o);
    if (lane == 0) dst[gwarp] = s * (1.0f / 64.0f);
}

// ---------------- w16 prep ----------------
__global__ void w16_kernel(const float* __restrict__ wm)
{
    int r = blockIdx.x, k = threadIdx.x;
    g_w16[r*256 + k] = __float2half(wm[(size_t)r*768 + 512 + k]);
}

// ---------------- batched-pointer fp32 GEMM (64x64 tile) ----------------
struct GArgs {
    const float* A[40];
    const float* B[40];
    float*       C[40];
    const float* bias[40];
};

template<bool TA, bool TB, bool BIAS>
__global__ void __launch_bounds__(256) gemm_b(
    GArgs ga, int lda, int ldb, int ldc, int K)
{
    __shared__ float As[16][68];
    __shared__ float Bs[16][68];
    int tid = threadIdx.x;
    int z = blockIdx.z;
    const float* Ab = ga.A[z];
    const float* Bb = ga.B[z];
    float* Cb       = ga.C[z];
    int m0 = blockIdx.y * 64, n0 = blockIdx.x * 64;
    float acc[4][4] = {};
    int tr = tid >> 4, tc = tid & 15;

    for (int k0 = 0; k0 < K; k0 += 16) {
        if (!TA) {
            int mm = tid >> 2, kq = (tid & 3) * 4;
            float4 v = *(const float4*)&Ab[(size_t)(m0+mm)*lda + k0 + kq];
            As[kq+0][mm]=v.x; As[kq+1][mm]=v.y; As[kq+2][mm]=v.z; As[kq+3][mm]=v.w;
        } else {
            int kk = tid >> 4, mq = (tid & 15) * 4;
            float4 v = *(const float4*)&Ab[(size_t)(k0+kk)*lda + m0 + mq];
            As[kk][mq+0]=v.x; As[kk][mq+1]=v.y; As[kk][mq+2]=v.z; As[kk][mq+3]=v.w;
        }
        if (!TB) {
            int kk = tid >> 4, nq = (tid & 15) * 4;
            float4 v = *(const float4*)&Bb[(size_t)(k0+kk)*ldb + n0 + nq];
            Bs[kk][nq+0]=v.x; Bs[kk][nq+1]=v.y; Bs[kk][nq+2]=v.z; Bs[kk][nq+3]=v.w;
        } else {
            int nn = tid >> 2, kq = (tid & 3) * 4;
            float4 v = *(const float4*)&Bb[(size_t)(n0+nn)*ldb + k0 + kq];
            Bs[kq+0][nn]=v.x; Bs[kq+1][nn]=v.y; Bs[kq+2][nn]=v.z; Bs[kq+3][nn]=v.w;
        }
        __syncthreads();
        #pragma unroll
        for (int k = 0; k < 16; k++) {
            float4 a4 = *(const float4*)&As[k][tr*4];
            float4 b4 = *(const float4*)&Bs[k][tc*4];
            float a[4] = {a4.x,a4.y,a4.z,a4.w};
            float b[4] = {b4.x,b4.y,b4.z,b4.w};
            #pragma unroll
            for (int i = 0; i < 4; i++)
                #pragma unroll
                for (int j = 0; j < 4; j++) acc[i][j] += a[i] * b[j];
        }
        __syncthreads();
    }
    #pragma unroll
    for (int i = 0; i < 4; i++) {
        float bv = BIAS ? ga.bias[z][m0 + tr*4 + i] : 0.0f;
        float4 v = { acc[i][0]+bv, acc[i][1]+bv, acc[i][2]+bv, acc[i][3]+bv };
        *(float4*)&Cb[(size_t)(m0+tr*4+i)*ldc + n0 + tc*4] = v;
    }
}

// ---------------- softmax over rows of 256 ----------------
__global__ void softmax_kernel()
{
    float* row = g_S + (size_t)blockIdx.x * 256;
    int tid = threadIdx.x;
    float v = row[tid];
    __shared__ float red[8];
    float mx = v;
    #pragma unroll
    for (int o = 16; o; o >>= 1) mx = fmaxf(mx, __shfl_xor_sync(0xffffffffu, mx, o));
    if ((tid & 31) == 0) red[tid >> 5] = mx;
    __syncthreads();
    float bmax = red[0];
    #pragma unroll
    for (int i = 1; i < 8; i++) bmax = fmaxf(bmax, red[i]);
    float e = expf(v - bmax);
    float s = e;
    #pragma unroll
    for (int o = 16; o; o >>= 1) s += __shfl_xor_sync(0xffffffffu, s, o);
    __syncthreads();
    if ((tid & 31) == 0) red[tid >> 5] = s;
    __syncthreads();
    float bsum = red[0];
    #pragma unroll
    for (int i = 1; i < 8; i++) bsum += red[i];
    row[tid] = e / bsum;
}

// ---------------- bfold ----------------
__global__ void bfold_kernel(const float* __restrict__ wm,
                             const float* __restrict__ bz,
                             const float* __restrict__ bm)
{
    int r = blockIdx.x * blockDim.x + threadIdx.x;
    if (r < 768) {
        float s = bm[r];
        for (int o = 0; o < 512; o++) s += wm[(size_t)r*768 + o] * bz[o];
        g_bf[r] = s;
    }
}

// ======== fused big GEMM (fp16 mma.m16n8k16) + bilinear G + gating ========
// Block = (y row, o-quarter m0=hh*64, batch). M=192 (3 slabs x 64 o), N=128 px,
// K=256 in 8 chunks of 32, double-buffered, one sync per chunk.
// SMEM words: A0 @0 (192x20), A1 @3840, B0 @7680 (128x17), B1 @9856. 48128 B.
__global__ void __launch_bounds__(256) fused_f16_gate(
    const float* __restrict__ m_in, float* __restrict__ out)
{
    __shared__ uint32_t sm[12032];
    int tid = threadIdx.x, lane = tid & 31, wid = tid >> 5;
    int y  = blockIdx.x;
    int m0 = blockIdx.y * 64;
    int b  = blockIdx.z;
    int wmi = wid >> 1, wni = wid & 1;
    int g = lane >> 2, tg = lane & 3;

    const __half* Xb = g_h16 + (size_t)b * 256 * HW_ + (size_t)y * 128;
    int kkp = tid >> 4, px8 = tid & 15;     // B staging task

    float acc[3][8][4];
    #pragma unroll
    for (int s = 0; s < 3; s++)
        #pragma unroll
        for (int n = 0; n < 8; n++)
            #pragma unroll
            for (int c = 0; c < 4; c++) acc[s][n][c] = 0.0f;

    uint4 va[3], blo, bhi;

    // ---- prologue: load + store chunk 0 ----
    #pragma unroll
    for (int i = 0; i < 3; i++) {
        int slot = tid + 256*i;
        int r = slot >> 2, q = slot & 3;
        int grow = (r >> 6) * 256 + m0 + (r & 63);
        va[i] = *(const uint4*)(g_w16 + (size_t)grow*256 + q*8);
    }
    blo = *(const uint4*)(Xb + (size_t)(2*kkp  ) * HW_ + px8*8);
    bhi = *(const uint4*)(Xb + (size_t)(2*kkp+1) * HW_ + px8*8);
    {
        #pragma unroll
        for (int i = 0; i < 3; i++) {
            int slot = tid + 256*i;
            int r = slot >> 2, q = slot & 3;
            *(uint4*)&sm[r*20 + q*4] = va[i];
        }
        const unsigned short* lp = (const unsigned short*)&blo;
        const unsigned short* hp = (const unsigned short*)&bhi;
        #pragma unroll
        for (int j = 0; j < 8; j++)
            sm[7680 + (px8*8 + j)*17 + kkp] = (uint32_t)lp[j] | ((uint32_t)hp[j] << 16);
    }
    __syncthreads();

    for (int c = 0; c < 8; c++) {
        if (c < 7) {
            int k0 = 32*(c+1);
            #pragma unroll
            for (int i = 0; i < 3; i++) {
                int slot = tid + 256*i;
                int r = slot >> 2, q = slot & 3;
                int grow = (r >> 6) * 256 + m0 + (r & 63);
                va[i] = *(const uint4*)(g_w16 + (size_t)grow*256 + k0 + q*8);
            }
            blo = *(const uint4*)(Xb + (size_t)(k0 + 2*kkp  ) * HW_ + px8*8);
            bhi = *(const uint4*)(Xb + (size_t)(k0 + 2*kkp+1) * HW_ + px8*8);
        }
        // ---- mma on buffer c&1 ----
        {
            uint32_t* A  = sm + (c & 1) * 3840;
            uint32_t* Bv = sm + 7680 + (c & 1) * 2176;
            #pragma unroll
            for (int ks = 0; ks < 2; ks++) {
                uint32_t bfr[8][2];
                #pragma unroll
                for (int nt = 0; nt < 8; nt++) {
                    int w = (wni*64 + nt*8 + g)*17 + ks*8 + tg;
                    bfr[nt][0] = Bv[w];
                    bfr[nt][1] = Bv[w + 4];
                }
                #pragma unroll
                for (int s = 0; s < 3; s++) {
                    int rb = s*64 + wmi*16;
                    uint32_t a0 = A[(rb + g    )*20 + ks*8 + tg    ];
                    uint32_t a1 = A[(rb + 8 + g)*20 + ks*8 + tg    ];
                    uint32_t a2 = A[(rb + g    )*20 + ks*8 + tg + 4];
                    uint32_t a3 = A[(rb + 8 + g)*20 + ks*8 + tg + 4];
                    #pragma unroll
                    for (int nt = 0; nt < 8; nt++)
                        asm volatile(
                            "mma.sync.aligned.m16n8k16.row.col.f32.f16.f16.f32 "
                            "{%0,%1,%2,%3},{%4,%5,%6,%7},{%8,%9},{%0,%1,%2,%3};\n"
                            : "+f"(acc[s][nt][0]), "+f"(acc[s][nt][1]),
                              "+f"(acc[s][nt][2]), "+f"(acc[s][nt][3])
                            : "r"(a0), "r"(a1), "r"(a2), "r"(a3),
                              "r"(bfr[nt][0]), "r"(bfr[nt][1]));
                }
            }
        }
        // ---- store next chunk into the idle buffer (read last in c-1) ----
        if (c < 7) {
            int nb = (c + 1) & 1;
            uint32_t* A  = sm + nb * 3840;
            uint32_t* Bv = sm + 7680 + nb * 2176;
            #pragma unroll
            for (int i = 0; i < 3; i++) {
                int slot = tid + 256*i;
                int r = slot >> 2, q = slot & 3;
                *(uint4*)&A[r*20 + q*4] = va[i];
            }
            const unsigned short* lp = (const unsigned short*)&blo;
            const unsigned short* hp = (const unsigned short*)&bhi;
            #pragma unroll
            for (int j = 0; j < 8; j++)
                Bv[(px8*8 + j)*17 + kkp] = (uint32_t)lp[j] | ((uint32_t)hp[j] << 16);
        }
        __syncthreads();
    }

    // ---- gy: y-interp of G rows (192 x 16) into smem ----
    float* gy = (float*)sm;
    float sy = (y + 0.5f) * 0.125f - 0.5f; if (sy < 0.0f) sy = 0.0f;
    int y0 = (int)sy; float fy = sy - (float)y0; int y1 = min(y0 + 1, 15);
    #pragma unroll
    for (int i = 0; i < 12; i++) {
        int idx = tid + 256*i;
        int r = idx >> 4, px16 = idx & 15;
        int grow = (r >> 6) * 256 + m0 + (r & 63);
        const float* Gb = g_G + ((size_t)b*768 + grow) * 256;
        gy[r*16 + px16] = (1.0f - fy) * Gb[y0*16 + px16] + fy * Gb[y1*16 + px16];
    }
    __syncthreads();

    // ---- gating epilogue ----
    const size_t OUT2 = (size_t)B_ * 256 * HW_;
    #pragma unroll
    for (int rr = 0; rr < 2; rr++) {
        int o_loc  = wmi*16 + g + rr*8;
        int o_glob = m0 + o_loc;
        float bv0 = g_bf[o_glob];
        float bv1 = g_bf[256 + o_glob];
        float bv2 = g_bf[512 + o_glob];
        const float* mrow = m_in + ((size_t)b*256 + o_glob)*HW_ + (size_t)y*128;
        float* hrow = out + ((size_t)b*256 + o_glob)*HW_ + (size_t)y*128;
        float* mrow_out = hrow + OUT2;
        #pragma unroll
        for (int nt = 0; nt < 8; nt++) {
            int x = wni*64 + nt*8 + tg*2;
            float2 mv = *(const float2*)&mrow[x];
            float nh[2], nm[2];
            #pragma unroll
            for (int px = 0; px < 2; px++) {
                int xx = x + px;
                float sx = (xx + 0.5f) * 0.125f - 0.5f; if (sx < 0.0f) sx = 0.0f;
                int x0 = (int)sx; float fx = sx - (float)x0; int x1 = min(x0 + 1, 15);
                float g0 = (1.0f-fx)*gy[(0*64+o_loc)*16 + x0] + fx*gy[(0*64+o_loc)*16 + x1];
                float g1 = (1.0f-fx)*gy[(1*64+o_loc)*16 + x0] + fx*gy[(1*64+o_loc)*16 + x1];
                float g2 = (1.0f-fx)*gy[(2*64+o_loc)*16 + x0] + fx*gy[(2*64+o_loc)*16 + x1];
                int cc = rr*2 + px;
                float mo = acc[0][nt][cc] + bv0 + g0;
                float mg = acc[1][nt][cc] + bv1 + g1;
                float mi = acc[2][nt][cc] + bv2 + g2;
                float mval = px ? mv.y : mv.x;
                float gi = 1.0f / (1.0f + expf(-mi));
                float nmv = (1.0f - gi) * mval + gi * tanhf(mg);
                nm[px] = nmv;
                nh[px] = nmv / (1.0f + expf(-mo));
            }
            *(float2*)&hrow[x]     = make_float2(nh[0], nh[1]);
            *(float2*)&mrow_out[x] = make_float2(nm[0], nm[1]);
        }
    }
}

// ---------------- launcher ----------------
extern "C" void kernel_launch(void* const* d_in, const int* in_sizes, int n_in,
                              void* d_out, int out_size)
{
    const float* h   = (const float*)d_in[0];
    const float* m   = (const float*)d_in[1];
    const float* wq  = (const float*)d_in[2];
    const float* bq  = (const float*)d_in[3];
    const float* wk  = (const float*)d_in[4];
    const float* bk  = (const float*)d_in[5];
    const float* wv  = (const float*)d_in[6];
    const float* bv  = (const float*)d_in[7];
    const float* wkm = (const float*)d_in[8];
    const float* bkm = (const float*)d_in[9];
    const float* wvm = (const float*)d_in[10];
    const float* bvm = (const float*)d_in[11];
    const float* wz  = (const float*)d_in[12];
    const float* bz  = (const float*)d_in[13];
    const float* wm  = (const float*)d_in[14];
    const float* bm  = (const float*)d_in[15];
    float* out = (float*)d_out;

    float *Hp, *Mp, *Yh, *Ym, *S, *ZT, *G, *Wzz;
    cudaGetSymbolAddress((void**)&Hp,  g_Hp);
    cudaGetSymbolAddress((void**)&Mp,  g_Mp);
    cudaGetSymbolAddress((void**)&Yh,  g_Yh);
    cudaGetSymbolAddress((void**)&Ym,  g_Ym);
    cudaGetSymbolAddress((void**)&S,   g_S);
    cudaGetSymbolAddress((void**)&ZT,  g_ZT);
    cudaGetSymbolAddress((void**)&G,   g_G);
    cudaGetSymbolAddress((void**)&Wzz, g_Wzz);

    // 1) pooling (+ h16 emit)
    pool_kernel<<<dim3(65536, 2), 256>>>(h, m);
    // 1b) w16 prep
    w16_kernel<<<768, 256>>>(wm);

    // 2) folded weights / bias
    {
        GArgs ga = {};
        ga.A[0] = wm; ga.B[0] = wz; ga.C[0] = Wzz;
        gemm_b<false,false,false><<<dim3(8,12,1), 256>>>(ga, 768, 512, 512, 512);
    }
    bfold_kernel<<<3, 256>>>(wm, bz, bm);

    // 3) all five projections in one launch
    {
        GArgs ga = {};
        const float* W5[5] = { wq, wk, wv, wkm, wvm };
        const float* b5[5] = { bq, bk, bv, bkm, bvm };
        for (int s = 0; s < 5; s++)
            for (int bt = 0; bt < 8; bt++) {
                int z = s*8 + bt;
                ga.A[z] = W5[s];
                ga.B[z] = (s < 3 ? Hp : Mp) + bt*PB;
                ga.C[z] = (s < 3) ? Yh + bt*3*PB + s*PB
                                  : Ym + bt*2*PB + (s-3)*PB;
                ga.bias[z] = b5[s];
            }
        gemm_b<false,false,true><<<dim3(4,4,40), 256>>>(ga, 256, 256, 256, 256);
    }

    // 4) scores
    {
        GArgs ga = {};
        for (int z = 0; z < 16; z++) {
            int bt = z & 7;
            ga.A[z] = Yh + bt*3*PB;
            ga.B[z] = (z < 8) ? Yh + bt*3*PB + PB : Ym + bt*2*PB;
            ga.C[z] = S + (long long)z*PB;
        }
        gemm_b<true,false,false><<<dim3(4,4,16), 256>>>(ga, 256, 256, 256, 256);
    }

    // 5) softmax
    softmax_kernel<<<4096, 256>>>();

    // 6) ZT = V @ A^T
    {
        GArgs ga = {};
        for (int z = 0; z < 16; z++) {
            int bt = z & 7;
            ga.A[z] = (z < 8) ? Yh + bt*3*PB + 2*PB : Ym + bt*2*PB + PB;
            ga.B[z] = S + (long long)z*PB;
            ga.C[z] = ZT + bt*2*PB + ((z < 8) ? 0 : PB);
        }
        gemm_b<false,true,false><<<dim3(4,4,16), 256>>>(ga, 256, 256, 256, 256);
    }

    // 7) G = Wzz @ ZTcat
    {
        GArgs ga = {};
        for (int bt = 0; bt < 8; bt++) {
            ga.A[bt] = Wzz;
            ga.B[bt] = ZT + bt*2*PB;
            ga.C[bt] = G + (long long)bt*768*256;
        }
        gemm_b<false,false,false><<<dim3(4,12,8), 256>>>(ga, 512, 256, 256, 512);
    }

    // 8) fused fp16-mma GEMM + upsample + gating -> outputs
    fused_f16_gate<<<dim3(128, 4, 8), 256>>>(m, out);
}

// round 9
// speedup vs baseline: 1.3526x; 1.1815x over previous
#include <cuda_runtime.h>
#include <cuda_fp16.h>
#include <cstdint>

#define B_   8
#define HW_  16384
#define PB   (256LL*256LL)

// ---------------- scratch ----------------
__device__ float g_Hp[B_*256*256];
__device__ float g_Mp[B_*256*256];
__device__ float g_Yh[B_*3*256*256];          // Qp,Kp,Vp per batch
__device__ float g_Ym[B_*2*256*256];          // Kmp,Vmp
__device__ float g_S [2*B_*256*256];          // scores/attn (h then m)
__device__ float g_ZT[B_*512*256];            // Zh rows 0..255, Zm 256..511 (d-major)
__device__ float g_G [B_*768*256];            // Wzz @ Zcat on 16x16 grid
__device__ float g_Wzz[768*512];
__device__ float g_bf[768];
__device__ __half g_h16[(size_t)B_*256*HW_]; // fp16 copy of h (64 MiB)
__device__ __half g_w16[768*256];            // fp16 copy of wm[:,512:768]

// ---------------- pooling (+ fp16 emit of h) ----------------
__global__ void pool_kernel(const float* __restrict__ h, const float* __restrict__ m)
{
    int gwarp = (blockIdx.x * blockDim.x + threadIdx.x) >> 5;
    int lane  = threadIdx.x & 31;
    const float* src = blockIdx.y ? m : h;
    float* dst       = blockIdx.y ? g_Mp : g_Hp;
    float2 v = *(const float2*)(src + (size_t)gwarp * 64 + lane * 2);
    if (blockIdx.y == 0)
        *(__half2*)(g_h16 + (size_t)gwarp * 64 + lane * 2) = __floats2half2_rn(v.x, v.y);
    float s = v.x + v.y;
    #pragma unroll
    for (int o = 16; o; o >>= 1) s += __shfl_xor_sync(0xffffffffu, s, o);
    if (lane == 0) dst[gwarp] = s * (1.0f / 64.0f);
}

// ---------------- w16 prep ----------------
__global__ void w16_kernel(const float* __restrict__ wm)
{
    int r = blockIdx.x, k = threadIdx.x;
    g_w16[r*256 + k] = __float2half(wm[(size_t)r*768 + 512 + k]);
}

// ---------------- batched-pointer fp32 GEMM (64x64 tile) ----------------
struct GArgs {
    const float* A[40];
    const float* B[40];
    float*       C[40];
    const float* bias[40];
};

template<bool TA, bool TB, bool BIAS>
__global__ void __launch_bounds__(256) gemm_b(
    GArgs ga, int lda, int ldb, int ldc, int K)
{
    __shared__ float As[16][68];
    __shared__ float Bs[16][68];
    int tid = threadIdx.x;
    int z = blockIdx.z;
    const float* Ab = ga.A[z];
    const float* Bb = ga.B[z];
    float* Cb       = ga.C[z];
    int m0 = blockIdx.y * 64, n0 = blockIdx.x * 64;
    float acc[4][4] = {};
    int tr = tid >> 4, tc = tid & 15;

    for (int k0 = 0; k0 < K; k0 += 16) {
        if (!TA) {
            int mm = tid >> 2, kq = (tid & 3) * 4;
            float4 v = *(const float4*)&Ab[(size_t)(m0+mm)*lda + k0 + kq];
            As[kq+0][mm]=v.x; As[kq+1][mm]=v.y; As[kq+2][mm]=v.z; As[kq+3][mm]=v.w;
        } else {
            int kk = tid >> 4, mq = (tid & 15) * 4;
            float4 v = *(const float4*)&Ab[(size_t)(k0+kk)*lda + m0 + mq];
            As[kk][mq+0]=v.x; As[kk][mq+1]=v.y; As[kk][mq+2]=v.z; As[kk][mq+3]=v.w;
        }
        if (!TB) {
            int kk = tid >> 4, nq = (tid & 15) * 4;
            float4 v = *(const float4*)&Bb[(size_t)(k0+kk)*ldb + n0 + nq];
            Bs[kk][nq+0]=v.x; Bs[kk][nq+1]=v.y; Bs[kk][nq+2]=v.z; Bs[kk][nq+3]=v.w;
        } else {
            int nn = tid >> 2, kq = (tid & 3) * 4;
            float4 v = *(const float4*)&Bb[(size_t)(n0+nn)*ldb + k0 + kq];
            Bs[kq+0][nn]=v.x; Bs[kq+1][nn]=v.y; Bs[kq+2][nn]=v.z; Bs[kq+3][nn]=v.w;
        }
        __syncthreads();
        #pragma unroll
        for (int k = 0; k < 16; k++) {
            float4 a4 = *(const float4*)&As[k][tr*4];
            float4 b4 = *(const float4*)&Bs[k][tc*4];
            float a[4] = {a4.x,a4.y,a4.z,a4.w};
            float b[4] = {b4.x,b4.y,b4.z,b4.w};
            #pragma unroll
            for (int i = 0; i < 4; i++)
                #pragma unroll
                for (int j = 0; j < 4; j++) acc[i][j] += a[i] * b[j];
        }
        __syncthreads();
    }
    #pragma unroll
    for (int i = 0; i < 4; i++) {
        float bv = BIAS ? ga.bias[z][m0 + tr*4 + i] : 0.0f;
        float4 v = { acc[i][0]+bv, acc[i][1]+bv, acc[i][2]+bv, acc[i][3]+bv };
        *(float4*)&Cb[(size_t)(m0+tr*4+i)*ldc + n0 + tc*4] = v;
    }
}

// ---------------- softmax over rows of 256 ----------------
__global__ void softmax_kernel()
{
    float* row = g_S + (size_t)blockIdx.x * 256;
    int tid = threadIdx.x;
    float v = row[tid];
    __shared__ float red[8];
    float mx = v;
    #pragma unroll
    for (int o = 16; o; o >>= 1) mx = fmaxf(mx, __shfl_xor_sync(0xffffffffu, mx, o));
    if ((tid & 31) == 0) red[tid >> 5] = mx;
    __syncthreads();
    float bmax = red[0];
    #pragma unroll
    for (int i = 1; i < 8; i++) bmax = fmaxf(bmax, red[i]);
    float e = expf(v - bmax);
    float s = e;
    #pragma unroll
    for (int o = 16; o; o >>= 1) s += __shfl_xor_sync(0xffffffffu, s, o);
    __syncthreads();
    if ((tid & 31) == 0) red[tid >> 5] = s;
    __syncthreads();
    float bsum = red[0];
    #pragma unroll
    for (int i = 1; i < 8; i++) bsum += red[i];
    row[tid] = e / bsum;
}

// ---------------- bfold (parallel): g_bf[r] = bm[r] + wm[r,:512].bz ------
__global__ void bfold_kernel(const float* __restrict__ wm,
                             const float* __restrict__ bz,
                             const float* __restrict__ bm)
{
    int r = blockIdx.x, t = threadIdx.x;
    float s = wm[(size_t)r*768 + t] * bz[t]
            + wm[(size_t)r*768 + 256 + t] * bz[256 + t];
    __shared__ float red[8];
    #pragma unroll
    for (int o = 16; o; o >>= 1) s += __shfl_xor_sync(0xffffffffu, s, o);
    if ((t & 31) == 0) red[t >> 5] = s;
    __syncthreads();
    if (t == 0) {
        float tot = bm[r];
        #pragma unroll
        for (int i = 0; i < 8; i++) tot += red[i];
        g_bf[r] = tot;
    }
}

// ======== fused big GEMM (fp16 mma.m16n8k16) + bilinear G + gating ========
// 512 threads, 4x4 warp grid; block tile M=192 (3 slabs x 64 o) x N=128 px.
// K=256 in 8 chunks of 32, double-buffered; acc 48/thread (no spills).
// SMEM words: A0 @0 (192x20), A1 @3840, B0 @7680 (128x17), B1 @9856.
__global__ void __launch_bounds__(512) fused_f16_gate(
    const float* __restrict__ m_in, float* __restrict__ out)
{
    __shared__ uint32_t sm[12032];
    int tid = threadIdx.x, lane = tid & 31, wid = tid >> 5;
    int y  = blockIdx.x;
    int m0 = blockIdx.y * 64;
    int b  = blockIdx.z;
    int wmi = wid >> 2, wni = wid & 3;           // 4 x 4
    int g = lane >> 2, tg = lane & 3;

    const __half* Xb = g_h16 + (size_t)b * 256 * HW_ + (size_t)y * 128;
    bool doB = tid < 256;
    int kkp = (tid & 255) >> 4, px8 = tid & 15;  // B staging task (tid<256)

    float acc[3][4][4];
    #pragma unroll
    for (int s = 0; s < 3; s++)
        #pragma unroll
        for (int n = 0; n < 4; n++)
            #pragma unroll
            for (int c = 0; c < 4; c++) acc[s][n][c] = 0.0f;

    uint4 va0, va1, blo, bhi;

    // A: 768 uint4/chunk: slot=tid (all), slot=512+tid (tid<256)
    int r0s = tid >> 2,        q0 = tid & 3;
    int r1s = (512 + tid) >> 2, q1 = tid & 3;    // (512+tid)&3 == tid&3
    int grow0 = (r0s >> 6) * 256 + m0 + (r0s & 63);
    int grow1 = (r1s >> 6) * 256 + m0 + (r1s & 63);

    // ---- prologue: load + store chunk 0 ----
    va0 = *(const uint4*)(g_w16 + (size_t)grow0*256 + q0*8);
    if (doB) {
        va1 = *(const uint4*)(g_w16 + (size_t)grow1*256 + q1*8);
        blo = *(const uint4*)(Xb + (size_t)(2*kkp  ) * HW_ + px8*8);
        bhi = *(const uint4*)(Xb + (size_t)(2*kkp+1) * HW_ + px8*8);
    }
    {
        *(uint4*)&sm[r0s*20 + q0*4] = va0;
        if (doB) {
            *(uint4*)&sm[r1s*20 + q1*4] = va1;
            const unsigned short* lp = (const unsigned short*)&blo;
            const unsigned short* hp = (const unsigned short*)&bhi;
            #pragma unroll
            for (int j = 0; j < 8; j++)
                sm[7680 + (px8*8 + j)*17 + kkp] = (uint32_t)lp[j] | ((uint32_t)hp[j] << 16);
        }
    }
    __syncthreads();

    for (int c = 0; c < 8; c++) {
        if (c < 7) {
            int k0 = 32*(c+1);
            va0 = *(const uint4*)(g_w16 + (size_t)grow0*256 + k0 + q0*8);
            if (doB) {
                va1 = *(const uint4*)(g_w16 + (size_t)grow1*256 + k0 + q1*8);
                blo = *(const uint4*)(Xb + (size_t)(k0 + 2*kkp  ) * HW_ + px8*8);
                bhi = *(const uint4*)(Xb + (size_t)(k0 + 2*kkp+1) * HW_ + px8*8);
            }
        }
        // ---- mma on buffer c&1 ----
        {
            uint32_t* A  = sm + (c & 1) * 3840;
            uint32_t* Bv = sm + 7680 + (c & 1) * 2176;
            #pragma unroll
            for (int ks = 0; ks < 2; ks++) {
                uint32_t bfr[4][2];
                #pragma unroll
                for (int nt = 0; nt < 4; nt++) {
                    int w = (wni*32 + nt*8 + g)*17 + ks*8 + tg;
                    bfr[nt][0] = Bv[w];
                    bfr[nt][1] = Bv[w + 4];
                }
                #pragma unroll
                for (int s = 0; s < 3; s++) {
                    int rb = s*64 + wmi*16;
                    uint32_t a0 = A[(rb + g    )*20 + ks*8 + tg    ];
                    uint32_t a1 = A[(rb + 8 + g)*20 + ks*8 + tg    ];
                    uint32_t a2 = A[(rb + g    )*20 + ks*8 + tg + 4];
                    uint32_t a3 = A[(rb + 8 + g)*20 + ks*8 + tg + 4];
                    #pragma unroll
                    for (int nt = 0; nt < 4; nt++)
                        asm volatile(
                            "mma.sync.aligned.m16n8k16.row.col.f32.f16.f16.f32 "
                            "{%0,%1,%2,%3},{%4,%5,%6,%7},{%8,%9},{%0,%1,%2,%3};\n"
                            : "+f"(acc[s][nt][0]), "+f"(acc[s][nt][1]),
                              "+f"(acc[s][nt][2]), "+f"(acc[s][nt][3])
                            : "r"(a0), "r"(a1), "r"(a2), "r"(a3),
                              "r"(bfr[nt][0]), "r"(bfr[nt][1]));
                }
            }
        }
        // ---- store next chunk into idle buffer ----
        if (c < 7) {
            int nb = (c + 1) & 1;
            uint32_t* A  = sm + nb * 3840;
            uint32_t* Bv = sm + 7680 + nb * 2176;
            *(uint4*)&A[r0s*20 + q0*4] = va0;
            if (doB) {
                *(uint4*)&A[r1s*20 + q1*4] = va1;
                const unsigned short* lp = (const unsigned short*)&blo;
                const unsigned short* hp = (const unsigned short*)&bhi;
                #pragma unroll
                for (int j = 0; j < 8; j++)
                    Bv[(px8*8 + j)*17 + kkp] = (uint32_t)lp[j] | ((uint32_t)hp[j] << 16);
            }
        }
        __syncthreads();
    }

    // ---- gy: y-interp of G rows (192 x 16) into smem ----
    float* gy = (float*)sm;
    float sy = (y + 0.5f) * 0.125f - 0.5f; if (sy < 0.0f) sy = 0.0f;
    int y0 = (int)sy; float fy = sy - (float)y0; int y1 = min(y0 + 1, 15);
    #pragma unroll
    for (int i = 0; i < 6; i++) {
        int idx = tid + 512*i;
        int r = idx >> 4, px16 = idx & 15;
        int grow = (r >> 6) * 256 + m0 + (r & 63);
        const float* Gb = g_G + ((size_t)b*768 + grow) * 256;
        gy[r*16 + px16] = (1.0f - fy) * Gb[y0*16 + px16] + fy * Gb[y1*16 + px16];
    }
    __syncthreads();

    // ---- gating epilogue ----
    const size_t OUT2 = (size_t)B_ * 256 * HW_;
    #pragma unroll
    for (int rr = 0; rr < 2; rr++) {
        int o_loc  = wmi*16 + g + rr*8;
        int o_glob = m0 + o_loc;
        float bv0 = g_bf[o_glob];
        float bv1 = g_bf[256 + o_glob];
        float bv2 = g_bf[512 + o_glob];
        const float* mrow = m_in + ((size_t)b*256 + o_glob)*HW_ + (size_t)y*128;
        float* hrow = out + ((size_t)b*256 + o_glob)*HW_ + (size_t)y*128;
        float* mrow_out = hrow + OUT2;
        #pragma unroll
        for (int nt = 0; nt < 4; nt++) {
            int x = wni*32 + nt*8 + tg*2;
            float2 mv = *(const float2*)&mrow[x];
            float nh[2], nm[2];
            #pragma unroll
            for (int px = 0; px < 2; px++) {
                int xx = x + px;
                float sx = (xx + 0.5f) * 0.125f - 0.5f; if (sx < 0.0f) sx = 0.0f;
                int x0 = (int)sx; float fx = sx - (float)x0; int x1 = min(x0 + 1, 15);
                float g0 = (1.0f-fx)*gy[(0*64+o_loc)*16 + x0] + fx*gy[(0*64+o_loc)*16 + x1];
                float g1 = (1.0f-fx)*gy[(1*64+o_loc)*16 + x0] + fx*gy[(1*64+o_loc)*16 + x1];
                float g2 = (1.0f-fx)*gy[(2*64+o_loc)*16 + x0] + fx*gy[(2*64+o_loc)*16 + x1];
                int cc = rr*2 + px;
                float mo = acc[0][nt][cc] + bv0 + g0;
                float mg = acc[1][nt][cc] + bv1 + g1;
                float mi = acc[2][nt][cc] + bv2 + g2;
                float mval = px ? mv.y : mv.x;
                float gi = 1.0f / (1.0f + expf(-mi));
                float nmv = (1.0f - gi) * mval + gi * tanhf(mg);
                nm[px] = nmv;
                nh[px] = nmv / (1.0f + expf(-mo));
            }
            *(float2*)&hrow[x]     = make_float2(nh[0], nh[1]);
            *(float2*)&mrow_out[x] = make_float2(nm[0], nm[1]);
        }
    }
}

// ---------------- launcher ----------------
extern "C" void kernel_launch(void* const* d_in, const int* in_sizes, int n_in,
                              void* d_out, int out_size)
{
    const float* h   = (const float*)d_in[0];
    const float* m   = (const float*)d_in[1];
    const float* wq  = (const float*)d_in[2];
    const float* bq  = (const float*)d_in[3];
    const float* wk  = (const float*)d_in[4];
    const float* bk  = (const float*)d_in[5];
    const float* wv  = (const float*)d_in[6];
    const float* bv  = (const float*)d_in[7];
    const float* wkm = (const float*)d_in[8];
    const float* bkm = (const float*)d_in[9];
    const float* wvm = (const float*)d_in[10];
    const float* bvm = (const float*)d_in[11];
    const float* wz  = (const float*)d_in[12];
    const float* bz  = (const float*)d_in[13];
    const float* wm  = (const float*)d_in[14];
    const float* bm  = (const float*)d_in[15];
    float* out = (float*)d_out;

    float *Hp, *Mp, *Yh, *Ym, *S, *ZT, *G, *Wzz;
    cudaGetSymbolAddress((void**)&Hp,  g_Hp);
    cudaGetSymbolAddress((void**)&Mp,  g_Mp);
    cudaGetSymbolAddress((void**)&Yh,  g_Yh);
    cudaGetSymbolAddress((void**)&Ym,  g_Ym);
    cudaGetSymbolAddress((void**)&S,   g_S);
    cudaGetSymbolAddress((void**)&ZT,  g_ZT);
    cudaGetSymbolAddress((void**)&G,   g_G);
    cudaGetSymbolAddress((void**)&Wzz, g_Wzz);

    // 1) pooling (+ h16 emit) and weight prep
    pool_kernel<<<dim3(65536, 2), 256>>>(h, m);
    w16_kernel<<<768, 256>>>(wm);

    // 2) folded weights / bias
    {
        GArgs ga = {};
        ga.A[0] = wm; ga.B[0] = wz; ga.C[0] = Wzz;
        gemm_b<false,false,false><<<dim3(8,12,1), 256>>>(ga, 768, 512, 512, 512);
    }
    bfold_kernel<<<768, 256>>>(wm, bz, bm);

    // 3) all five projections in one launch
    {
        GArgs ga = {};
        const float* W5[5] = { wq, wk, wv, wkm, wvm };
        const float* b5[5] = { bq, bk, bv, bkm, bvm };
        for (int s = 0; s < 5; s++)
            for (int bt = 0; bt < 8; bt++) {
                int z = s*8 + bt;
                ga.A[z] = W5[s];
                ga.B[z] = (s < 3 ? Hp : Mp) + bt*PB;
                ga.C[z] = (s < 3) ? Yh + bt*3*PB + s*PB
                                  : Ym + bt*2*PB + (s-3)*PB;
                ga.bias[z] = b5[s];
            }
        gemm_b<false,false,true><<<dim3(4,4,40), 256>>>(ga, 256, 256, 256, 256);
    }

    // 4) scores
    {
        GArgs ga = {};
        for (int z = 0; z < 16; z++) {
            int bt = z & 7;
            ga.A[z] = Yh + bt*3*PB;
            ga.B[z] = (z < 8) ? Yh + bt*3*PB + PB : Ym + bt*2*PB;
            ga.C[z] = S + (long long)z*PB;
        }
        gemm_b<true,false,false><<<dim3(4,4,16), 256>>>(ga, 256, 256, 256, 256);
    }

    // 5) softmax
    softmax_kernel<<<4096, 256>>>();

    // 6) ZT = V @ A^T
    {
        GArgs ga = {};
        for (int z = 0; z < 16; z++) {
            int bt = z & 7;
            ga.A[z] = (z < 8) ? Yh + bt*3*PB + 2*PB : Ym + bt*2*PB + PB;
            ga.B[z] = S + (long long)z*PB;
            ga.C[z] = ZT + bt*2*PB + ((z < 8) ? 0 : PB);
        }
        gemm_b<false,true,false><<<dim3(4,4,16), 256>>>(ga, 256, 256, 256, 256);
    }

    // 7) G = Wzz @ ZTcat
    {
        GArgs ga = {};
        for (int bt = 0; bt < 8; bt++) {
            ga.A[bt] = Wzz;
            ga.B[bt] = ZT + bt*2*PB;
            ga.C[bt] = G + (long long)bt*768*256;
        }
        gemm_b<false,false,false><<<dim3(4,12,8), 256>>>(ga, 512, 256, 256, 512);
    }

    // 8) fused fp16-mma GEMM + upsample + gating -> outputs
    fused_f16_gate<<<dim3(128, 4, 8), 512>>>(m, out);
}

// round 10
// speedup vs baseline: 1.4283x; 1.0559x over previous
#include <cuda_runtime.h>
#include <cuda_fp16.h>
#include <cstdint>

#define B_   8
#define HW_  16384
#define PB   (256LL*256LL)

// ---------------- scratch ----------------
__device__ float g_Hp[B_*256*256];
__device__ float g_Mp[B_*256*256];
__device__ float g_Yh[B_*3*256*256];          // Qp,Kp,Vp per batch
__device__ float g_Ym[B_*2*256*256];          // Kmp,Vmp
__device__ float g_S [2*B_*256*256];          // scores/attn (h then m)
__device__ float g_ZT[B_*512*256];            // Zh rows 0..255, Zm 256..511 (d-major)
__device__ float g_G [B_*768*256];            // Wzz @ Zcat on 16x16 grid
__device__ float g_Wzz[768*512];
__device__ float g_bf[768];
__device__ __half g_h16[(size_t)B_*256*HW_]; // fp16 copy of h (64 MiB)
__device__ __half g_m16[(size_t)B_*256*HW_]; // fp16 copy of m (64 MiB)
__device__ __half g_w16[768*256];            // fp16 copy of wm[:,512:768]

// ---------------- pooling: MLP-4 half-warp-per-strip + fp16 emit ---------
// Half-warp (16 lanes) handles 4 consecutive strips of 64 floats.
// Loads: 4 independent float4 per thread (front-batched -> MLP=4).
__global__ void pool_kernel(const float* __restrict__ h, const float* __restrict__ m)
{
    int tid = threadIdx.x;
    int hw = tid >> 4, l16 = tid & 15;
    const float* src = blockIdx.y ? m : h;
    float*  dst  = blockIdx.y ? g_Mp  : g_Hp;
    __half* d16  = blockIdx.y ? g_m16 : g_h16;
    int gh = blockIdx.x * 16 + hw;          // global half-warp id
    int s0 = gh * 4;                        // first strip

    float4 v[4];
    #pragma unroll
    for (int j = 0; j < 4; j++)
        v[j] = *(const float4*)(src + (size_t)(s0 + j) * 64 + l16 * 4);

    #pragma unroll
    for (int j = 0; j < 4; j++) {
        __half2 p0 = __floats2half2_rn(v[j].x, v[j].y);
        __half2 p1 = __floats2half2_rn(v[j].z, v[j].w);
        uint2 u;
        u.x = *(const uint32_t*)&p0;
        u.y = *(const uint32_t*)&p1;
        *(uint2*)(d16 + (size_t)(s0 + j) * 64 + l16 * 4) = u;
    }

    #pragma unroll
    for (int j = 0; j < 4; j++) {
        float s = v[j].x + v[j].y + v[j].z + v[j].w;
        #pragma unroll
        for (int o = 8; o; o >>= 1) s += __shfl_xor_sync(0xffffffffu, s, o);
        if (l16 == 0) dst[s0 + j] = s * (1.0f / 64.0f);
    }
}

// ---------------- w16 prep ----------------
__global__ void w16_kernel(const float* __restrict__ wm)
{
    int r = blockIdx.x, k = threadIdx.x;
    g_w16[r*256 + k] = __float2half(wm[(size_t)r*768 + 512 + k]);
}

// ---------------- batched-pointer fp32 GEMM (64x64 tile) ----------------
struct GArgs {
    const float* A[40];
    const float* B[40];
    float*       C[40];
    const float* bias[40];
};

template<bool TA, bool TB, bool BIAS>
__global__ void __launch_bounds__(256) gemm_b(
    GArgs ga, int lda, int ldb, int ldc, int K)
{
    __shared__ float As[16][68];
    __shared__ float Bs[16][68];
    int tid = threadIdx.x;
    int z = blockIdx.z;
    const float* Ab = ga.A[z];
    const float* Bb = ga.B[z];
    float* Cb       = ga.C[z];
    int m0 = blockIdx.y * 64, n0 = blockIdx.x * 64;
    float acc[4][4] = {};
    int tr = tid >> 4, tc = tid & 15;

    for (int k0 = 0; k0 < K; k0 += 16) {
        if (!TA) {
            int mm = tid >> 2, kq = (tid & 3) * 4;
            float4 v = *(const float4*)&Ab[(size_t)(m0+mm)*lda + k0 + kq];
            As[kq+0][mm]=v.x; As[kq+1][mm]=v.y; As[kq+2][mm]=v.z; As[kq+3][mm]=v.w;
        } else {
            int kk = tid >> 4, mq = (tid & 15) * 4;
            float4 v = *(const float4*)&Ab[(size_t)(k0+kk)*lda + m0 + mq];
            As[kk][mq+0]=v.x; As[kk][mq+1]=v.y; As[kk][mq+2]=v.z; As[kk][mq+3]=v.w;
        }
        if (!TB) {
            int kk = tid >> 4, nq = (tid & 15) * 4;
            float4 v = *(const float4*)&Bb[(size_t)(k0+kk)*ldb + n0 + nq];
            Bs[kk][nq+0]=v.x; Bs[kk][nq+1]=v.y; Bs[kk][nq+2]=v.z; Bs[kk][nq+3]=v.w;
        } else {
            int nn = tid >> 2, kq = (tid & 3) * 4;
            float4 v = *(const float4*)&Bb[(size_t)(n0+nn)*ldb + k0 + kq];
            Bs[kq+0][nn]=v.x; Bs[kq+1][nn]=v.y; Bs[kq+2][nn]=v.z; Bs[kq+3][nn]=v.w;
        }
        __syncthreads();
        #pragma unroll
        for (int k = 0; k < 16; k++) {
            float4 a4 = *(const float4*)&As[k][tr*4];
            float4 b4 = *(const float4*)&Bs[k][tc*4];
            float a[4] = {a4.x,a4.y,a4.z,a4.w};
            float b[4] = {b4.x,b4.y,b4.z,b4.w};
            #pragma unroll
            for (int i = 0; i < 4; i++)
                #pragma unroll
                for (int j = 0; j < 4; j++) acc[i][j] += a[i] * b[j];
        }
        __syncthreads();
    }
    #pragma unroll
    for (int i = 0; i < 4; i++) {
        float bv = BIAS ? ga.bias[z][m0 + tr*4 + i] : 0.0f;
        float4 v = { acc[i][0]+bv, acc[i][1]+bv, acc[i][2]+bv, acc[i][3]+bv };
        *(float4*)&Cb[(size_t)(m0+tr*4+i)*ldc + n0 + tc*4] = v;
    }
}

// ---------------- softmax over rows of 256 ----------------
__global__ void softmax_kernel()
{
    float* row = g_S + (size_t)blockIdx.x * 256;
    int tid = threadIdx.x;
    float v = row[tid];
    __shared__ float red[8];
    float mx = v;
    #pragma unroll
    for (int o = 16; o; o >>= 1) mx = fmaxf(mx, __shfl_xor_sync(0xffffffffu, mx, o));
    if ((tid & 31) == 0) red[tid >> 5] = mx;
    __syncthreads();
    float bmax = red[0];
    #pragma unroll
    for (int i = 1; i < 8; i++) bmax = fmaxf(bmax, red[i]);
    float e = expf(v - bmax);
    float s = e;
    #pragma unroll
    for (int o = 16; o; o >>= 1) s += __shfl_xor_sync(0xffffffffu, s, o);
    __syncthreads();
    if ((tid & 31) == 0) red[tid >> 5] = s;
    __syncthreads();
    float bsum = red[0];
    #pragma unroll
    for (int i = 1; i < 8; i++) bsum += red[i];
    row[tid] = e / bsum;
}

// ---------------- bfold (parallel) ----------------
__global__ void bfold_kernel(const float* __restrict__ wm,
                             const float* __restrict__ bz,
                             const float* __restrict__ bm)
{
    int r = blockIdx.x, t = threadIdx.x;
    float s = wm[(size_t)r*768 + t] * bz[t]
            + wm[(size_t)r*768 + 256 + t] * bz[256 + t];
    __shared__ float red[8];
    #pragma unroll
    for (int o = 16; o; o >>= 1) s += __shfl_xor_sync(0xffffffffu, s, o);
    if ((t & 31) == 0) red[t >> 5] = s;
    __syncthreads();
    if (t == 0) {
        float tot = bm[r];
        #pragma unroll
        for (int i = 0; i < 8; i++) tot += red[i];
        g_bf[r] = tot;
    }
}

// ======== fused big GEMM (fp16 mma.m16n8k16) + bilinear G + gating ========
__global__ void __launch_bounds__(512) fused_f16_gate(float* __restrict__ out)
{
    __shared__ uint32_t sm[12032];
    int tid = threadIdx.x, lane = tid & 31, wid = tid >> 5;
    int y  = blockIdx.x;
    int m0 = blockIdx.y * 64;
    int b  = blockIdx.z;
    int wmi = wid >> 2, wni = wid & 3;           // 4 x 4
    int g = lane >> 2, tg = lane & 3;

    const __half* Xb = g_h16 + (size_t)b * 256 * HW_ + (size_t)y * 128;
    bool doB = tid < 256;
    int kkp = (tid & 255) >> 4, px8 = tid & 15;

    float acc[3][4][4];
    #pragma unroll
    for (int s = 0; s < 3; s++)
        #pragma unroll
        for (int n = 0; n < 4; n++)
            #pragma unroll
            for (int c = 0; c < 4; c++) acc[s][n][c] = 0.0f;

    uint4 va0, va1, blo, bhi;

    int r0s = tid >> 2,         q0 = tid & 3;
    int r1s = (512 + tid) >> 2, q1 = tid & 3;
    int grow0 = (r0s >> 6) * 256 + m0 + (r0s & 63);
    int grow1 = (r1s >> 6) * 256 + m0 + (r1s & 63);

    va0 = *(const uint4*)(g_w16 + (size_t)grow0*256 + q0*8);
    if (doB) {
        va1 = *(const uint4*)(g_w16 + (size_t)grow1*256 + q1*8);
        blo = *(const uint4*)(Xb + (size_t)(2*kkp  ) * HW_ + px8*8);
        bhi = *(const uint4*)(Xb + (size_t)(2*kkp+1) * HW_ + px8*8);
    }
    {
        *(uint4*)&sm[r0s*20 + q0*4] = va0;
        if (doB) {
            *(uint4*)&sm[r1s*20 + q1*4] = va1;
            const unsigned short* lp = (const unsigned short*)&blo;
            const unsigned short* hp = (const unsigned short*)&bhi;
            #pragma unroll
            for (int j = 0; j < 8; j++)
                sm[7680 + (px8*8 + j)*17 + kkp] = (uint32_t)lp[j] | ((uint32_t)hp[j] << 16);
        }
    }
    __syncthreads();

    for (int c = 0; c < 8; c++) {
        if (c < 7) {
            int k0 = 32*(c+1);
            va0 = *(const uint4*)(g_w16 + (size_t)grow0*256 + k0 + q0*8);
            if (doB) {
                va1 = *(const uint4*)(g_w16 + (size_t)grow1*256 + k0 + q1*8);
                blo = *(const uint4*)(Xb + (size_t)(k0 + 2*kkp  ) * HW_ + px8*8);
                bhi = *(const uint4*)(Xb + (size_t)(k0 + 2*kkp+1) * HW_ + px8*8);
            }
        }
        {
            uint32_t* A  = sm + (c & 1) * 3840;
            uint32_t* Bv = sm + 7680 + (c & 1) * 2176;
            #pragma unroll
            for (int ks = 0; ks < 2; ks++) {
                uint32_t bfr[4][2];
                #pragma unroll
                for (int nt = 0; nt < 4; nt++) {
                    int w = (wni*32 + nt*8 + g)*17 + ks*8 + tg;
                    bfr[nt][0] = Bv[w];
                    bfr[nt][1] = Bv[w + 4];
                }
                #pragma unroll
                for (int s = 0; s < 3; s++) {
                    int rb = s*64 + wmi*16;
                    uint32_t a0 = A[(rb + g    )*20 + ks*8 + tg    ];
                    uint32_t a1 = A[(rb + 8 + g)*20 + ks*8 + tg    ];
                    uint32_t a2 = A[(rb + g    )*20 + ks*8 + tg + 4];
                    uint32_t a3 = A[(rb + 8 + g)*20 + ks*8 + tg + 4];
                    #pragma unroll
                    for (int nt = 0; nt < 4; nt++)
                        asm volatile(
                            "mma.sync.aligned.m16n8k16.row.col.f32.f16.f16.f32 "
                            "{%0,%1,%2,%3},{%4,%5,%6,%7},{%8,%9},{%0,%1,%2,%3};\n"
                            : "+f"(acc[s][nt][0]), "+f"(acc[s][nt][1]),
                              "+f"(acc[s][nt][2]), "+f"(acc[s][nt][3])
                            : "r"(a0), "r"(a1), "r"(a2), "r"(a3),
                              "r"(bfr[nt][0]), "r"(bfr[nt][1]));
                }
            }
        }
        if (c < 7) {
            int nb = (c + 1) & 1;
            uint32_t* A  = sm + nb * 3840;
            uint32_t* Bv = sm + 7680 + nb * 2176;
            *(uint4*)&A[r0s*20 + q0*4] = va0;
            if (doB) {
                *(uint4*)&A[r1s*20 + q1*4] = va1;
                const unsigned short* lp = (const unsigned short*)&blo;
                const unsigned short* hp = (const unsigned short*)&bhi;
                #pragma unroll
                for (int j = 0; j < 8; j++)
                    Bv[(px8*8 + j)*17 + kkp] = (uint32_t)lp[j] | ((uint32_t)hp[j] << 16);
            }
        }
        __syncthreads();
    }

    // ---- gy: y-interp of G rows (192 x 16) into smem ----
    float* gy = (float*)sm;
    float sy = (y + 0.5f) * 0.125f - 0.5f; if (sy < 0.0f) sy = 0.0f;
    int y0 = (int)sy; float fy = sy - (float)y0; int y1 = min(y0 + 1, 15);
    #pragma unroll
    for (int i = 0; i < 6; i++) {
        int idx = tid + 512*i;
        int r = idx >> 4, px16 = idx & 15;
        int grow = (r >> 6) * 256 + m0 + (r & 63);
        const float* Gb = g_G + ((size_t)b*768 + grow) * 256;
        gy[r*16 + px16] = (1.0f - fy) * Gb[y0*16 + px16] + fy * Gb[y1*16 + px16];
    }
    __syncthreads();

    // ---- gating epilogue (m read as fp16) ----
    const size_t OUT2 = (size_t)B_ * 256 * HW_;
    #pragma unroll
    for (int rr = 0; rr < 2; rr++) {
        int o_loc  = wmi*16 + g + rr*8;
        int o_glob = m0 + o_loc;
        float bv0 = g_bf[o_glob];
        float bv1 = g_bf[256 + o_glob];
        float bv2 = g_bf[512 + o_glob];
        const __half* mrow = g_m16 + ((size_t)b*256 + o_glob)*HW_ + (size_t)y*128;
        float* hrow = out + ((size_t)b*256 + o_glob)*HW_ + (size_t)y*128;
        float* mrow_out = hrow + OUT2;
        #pragma unroll
        for (int nt = 0; nt < 4; nt++) {
            int x = wni*32 + nt*8 + tg*2;
            __half2 mh = *(const __half2*)&mrow[x];
            float2 mv = __half22float2(mh);
            float nh[2], nm[2];
            #pragma unroll
            for (int px = 0; px < 2; px++) {
                int xx = x + px;
                float sx = (xx + 0.5f) * 0.125f - 0.5f; if (sx < 0.0f) sx = 0.0f;
                int x0 = (int)sx; float fx = sx - (float)x0; int x1 = min(x0 + 1, 15);
                float g0 = (1.0f-fx)*gy[(0*64+o_loc)*16 + x0] + fx*gy[(0*64+o_loc)*16 + x1];
                float g1 = (1.0f-fx)*gy[(1*64+o_loc)*16 + x0] + fx*gy[(1*64+o_loc)*16 + x1];
                float g2 = (1.0f-fx)*gy[(2*64+o_loc)*16 + x0] + fx*gy[(2*64+o_loc)*16 + x1];
                int cc = rr*2 + px;
                float mo = acc[0][nt][cc] + bv0 + g0;
                float mg = acc[1][nt][cc] + bv1 + g1;
                float mi = acc[2][nt][cc] + bv2 + g2;
                float mval = px ? mv.y : mv.x;
                float gi = 1.0f / (1.0f + expf(-mi));
                float nmv = (1.0f - gi) * mval + gi * tanhf(mg);
                nm[px] = nmv;
                nh[px] = nmv / (1.0f + expf(-mo));
            }
            *(float2*)&hrow[x]     = make_float2(nh[0], nh[1]);
            *(float2*)&mrow_out[x] = make_float2(nm[0], nm[1]);
        }
    }
}

// ---------------- launcher ----------------
extern "C" void kernel_launch(void* const* d_in, const int* in_sizes, int n_in,
                              void* d_out, int out_size)
{
    const float* h   = (const float*)d_in[0];
    const float* m   = (const float*)d_in[1];
    const float* wq  = (const float*)d_in[2];
    const float* bq  = (const float*)d_in[3];
    const float* wk  = (const float*)d_in[4];
    const float* bk  = (const float*)d_in[5];
    const float* wv  = (const float*)d_in[6];
    const float* bv  = (const float*)d_in[7];
    const float* wkm = (const float*)d_in[8];
    const float* bkm = (const float*)d_in[9];
    const float* wvm = (const float*)d_in[10];
    const float* bvm = (const float*)d_in[11];
    const float* wz  = (const float*)d_in[12];
    const float* bz  = (const float*)d_in[13];
    const float* wm  = (const float*)d_in[14];
    const float* bm  = (const float*)d_in[15];
    float* out = (float*)d_out;

    float *Hp, *Mp, *Yh, *Ym, *S, *ZT, *G, *Wzz;
    cudaGetSymbolAddress((void**)&Hp,  g_Hp);
    cudaGetSymbolAddress((void**)&Mp,  g_Mp);
    cudaGetSymbolAddress((void**)&Yh,  g_Yh);
    cudaGetSymbolAddress((void**)&Ym,  g_Ym);
    cudaGetSymbolAddress((void**)&S,   g_S);
    cudaGetSymbolAddress((void**)&ZT,  g_ZT);
    cudaGetSymbolAddress((void**)&G,   g_G);
    cudaGetSymbolAddress((void**)&Wzz, g_Wzz);

    // 1) pooling (+ h16/m16 emit) and weight prep
    pool_kernel<<<dim3(8192, 2), 256>>>(h, m);
    w16_kernel<<<768, 256>>>(wm);

    // 2) folded weights / bias
    {
        GArgs ga = {};
        ga.A[0] = wm; ga.B[0] = wz; ga.C[0] = Wzz;
        gemm_b<false,false,false><<<dim3(8,12,1), 256>>>(ga, 768, 512, 512, 512);
    }
    bfold_kernel<<<768, 256>>>(wm, bz, bm);

    // 3) all five projections in one launch
    {
        GArgs ga = {};
        const float* W5[5] = { wq, wk, wv, wkm, wvm };
        const float* b5[5] = { bq, bk, bv, bkm, bvm };
        for (int s = 0; s < 5; s++)
            for (int bt = 0; bt < 8; bt++) {
                int z = s*8 + bt;
                ga.A[z] = W5[s];
                ga.B[z] = (s < 3 ? Hp : Mp) + bt*PB;
                ga.C[z] = (s < 3) ? Yh + bt*3*PB + s*PB
                                  : Ym + bt*2*PB + (s-3)*PB;
                ga.bias[z] = b5[s];
            }
        gemm_b<false,false,true><<<dim3(4,4,40), 256>>>(ga, 256, 256, 256, 256);
    }

    // 4) scores
    {
        GArgs ga = {};
        for (int z = 0; z < 16; z++) {
            int bt = z & 7;
            ga.A[z] = Yh + bt*3*PB;
            ga.B[z] = (z < 8) ? Yh + bt*3*PB + PB : Ym + bt*2*PB;
            ga.C[z] = S + (long long)z*PB;
        }
        gemm_b<true,false,false><<<dim3(4,4,16), 256>>>(ga, 256, 256, 256, 256);
    }

    // 5) softmax
    softmax_kernel<<<4096, 256>>>();

    // 6) ZT = V @ A^T
    {
        GArgs ga = {};
        for (int z = 0; z < 16; z++) {
            int bt = z & 7;
            ga.A[z] = (z < 8) ? Yh + bt*3*PB + 2*PB : Ym + bt*2*PB + PB;
            ga.B[z] = S + (long long)z*PB;
            ga.C[z] = ZT + bt*2*PB + ((z < 8) ? 0 : PB);
        }
        gemm_b<false,true,false><<<dim3(4,4,16), 256>>>(ga, 256, 256, 256, 256);
    }

    // 7) G = Wzz @ ZTcat
    {
        GArgs ga = {};
        for (int bt = 0; bt < 8; bt++) {
            ga.A[bt] = Wzz;
            ga.B[bt] = ZT + bt*2*PB;
            ga.C[bt] = G + (long long)bt*768*256;
        }
        gemm_b<false,false,false><<<dim3(4,12,8), 256>>>(ga, 512, 256, 256, 512);
    }

    // 8) fused fp16-mma GEMM + upsample + gating -> outputs
    fused_f16_gate<<<dim3(128, 4, 8), 512>>>(out);
}

// round 11
// speedup vs baseline: 1.5249x; 1.0676x over previous
#include <cuda_runtime.h>
#include <cuda_fp16.h>
#include <cstdint>

#define B_   8
#define HW_  16384
#define PB   (256LL*256LL)

// ---------------- scratch ----------------
__device__ float  g_S [2*B_*256*256];         // scores (fp32, pre-softmax & post)
__device__ __half g_S16[2*B_*256*256];        // softmax probs fp16
__device__ float  g_ZT[B_*512*256];           // Zh rows 0..255, Zm 256..511 (d-major)
__device__ float  g_G [B_*768*256];           // Wzz @ Zcat on 16x16 grid
__device__ float  g_Wzz[768*512];
__device__ float  g_bf[768];
__device__ __half g_h16[(size_t)B_*256*HW_];  // fp16 h (64 MiB)
__device__ __half g_m16[(size_t)B_*256*HW_];  // fp16 m (64 MiB)
__device__ __half g_w16[768*256];             // fp16 wm[:,512:768]
__device__ __half g_W516[5*256*256];          // fp16 {wq,wk,wv,wkm,wvm}
__device__ __half g_HpT[B_*256*256];          // pooled h, TRANSPOSED [b][p][c]
__device__ __half g_MpT[B_*256*256];          // pooled m, TRANSPOSED [b][p][c]
__device__ __half g_QT [B_*256*256];          // Q^T  [b][p][d]
__device__ __half g_KT [B_*256*256];          // K^T  [b][q][d]
__device__ __half g_KmT[B_*256*256];          // Km^T [b][q][d]
__device__ __half g_V  [B_*256*256];          // V    [b][d][p]
__device__ __half g_Vm [B_*256*256];          // Vm   [b][d][p]

__device__ __forceinline__ float fast_tanh(float x) {
    float r; asm("tanh.approx.f32 %0, %1;" : "=f"(r) : "f"(x)); return r;
}
__device__ __forceinline__ float fast_sig(float x) {
    return 1.0f / (1.0f + __expf(-x));
}

// ---------------- pooling: MLP-4 + fp16 emit + transposed pooled --------
__global__ void pool_kernel(const float* __restrict__ h, const float* __restrict__ m)
{
    int tid = threadIdx.x;
    int hw = tid >> 4, l16 = tid & 15;
    const float* src = blockIdx.y ? m : h;
    __half* d16  = blockIdx.y ? g_m16 : g_h16;
    __half* dstT = blockIdx.y ? g_MpT : g_HpT;
    int gh = blockIdx.x * 16 + hw;
    int s0 = gh * 4;

    float4 v[4];
    #pragma unroll
    for (int j = 0; j < 4; j++)
        v[j] = *(const float4*)(src + (size_t)(s0 + j) * 64 + l16 * 4);

    #pragma unroll
    for (int j = 0; j < 4; j++) {
        __half2 p0 = __floats2half2_rn(v[j].x, v[j].y);
        __half2 p1 = __floats2half2_rn(v[j].z, v[j].w);
        uint2 u;
        u.x = *(const uint32_t*)&p0;
        u.y = *(const uint32_t*)&p1;
        *(uint2*)(d16 + (size_t)(s0 + j) * 64 + l16 * 4) = u;
    }

    #pragma unroll
    for (int j = 0; j < 4; j++) {
        float s = v[j].x + v[j].y + v[j].z + v[j].w;
        #pragma unroll
        for (int o = 8; o; o >>= 1) s += __shfl_xor_sync(0xffffffffu, s, o);
        if (l16 == 0) {
            int idx = s0 + j;   // (b*256 + c)*256 + p
            int off = (idx & 0xFF0000) | ((idx & 255) << 8) | ((idx >> 8) & 255);
            dstT[off] = __float2half(s * (1.0f / 64.0f));
        }
    }
}

// ---------------- weight fp16 prep ----------------
__global__ void w16_kernel(const float* __restrict__ wm)
{
    int r = blockIdx.x, k = threadIdx.x;
    g_w16[r*256 + k] = __float2half(wm[(size_t)r*768 + 512 + k]);
}

__global__ void w5_kernel(const float* __restrict__ w0, const float* __restrict__ w1,
                          const float* __restrict__ w2, const float* __restrict__ w3,
                          const float* __restrict__ w4)
{
    int idx = blockIdx.x * 256 + threadIdx.x;
    const float* w;
    switch (blockIdx.y) {
        case 0: w = w0; break;
        case 1: w = w1; break;
        case 2: w = w2; break;
        case 3: w = w3; break;
        default: w = w4; break;
    }
    g_W516[blockIdx.y * 65536 + idx] = __float2half(w[idx]);
}

// ---------------- batched-pointer fp32 GEMM (64x64 tile) ----------------
struct GArgs {
    const float* A[40];
    const float* B[40];
    float*       C[40];
    const float* bias[40];
};

template<bool TA, bool TB, bool BIAS>
__global__ void __launch_bounds__(256) gemm_b(
    GArgs ga, int lda, int ldb, int ldc, int K)
{
    __shared__ float As[16][68];
    __shared__ float Bs[16][68];
    int tid = threadIdx.x;
    int z = blockIdx.z;
    const float* Ab = ga.A[z];
    const float* Bb = ga.B[z];
    float* Cb       = ga.C[z];
    int m0 = blockIdx.y * 64, n0 = blockIdx.x * 64;
    float acc[4][4] = {};
    int tr = tid >> 4, tc = tid & 15;

    for (int k0 = 0; k0 < K; k0 += 16) {
        if (!TA) {
            int mm = tid >> 2, kq = (tid & 3) * 4;
            float4 v = *(const float4*)&Ab[(size_t)(m0+mm)*lda + k0 + kq];
            As[kq+0][mm]=v.x; As[kq+1][mm]=v.y; As[kq+2][mm]=v.z; As[kq+3][mm]=v.w;
        } else {
            int kk = tid >> 4, mq = (tid & 15) * 4;
            float4 v = *(const float4*)&Ab[(size_t)(k0+kk)*lda + m0 + mq];
            As[kk][mq+0]=v.x; As[kk][mq+1]=v.y; As[kk][mq+2]=v.z; As[kk][mq+3]=v.w;
        }
        if (!TB) {
            int kk = tid >> 4, nq = (tid & 15) * 4;
            float4 v = *(const float4*)&Bb[(size_t)(k0+kk)*ldb + n0 + nq];
            Bs[kk][nq+0]=v.x; Bs[kk][nq+1]=v.y; Bs[kk][nq+2]=v.z; Bs[kk][nq+3]=v.w;
        } else {
            int nn = tid >> 2, kq = (tid & 3) * 4;
            float4 v = *(const float4*)&Bb[(size_t)(n0+nn)*ldb + k0 + kq];
            Bs[kq+0][nn]=v.x; Bs[kq+1][nn]=v.y; Bs[kq+2][nn]=v.z; Bs[kq+3][nn]=v.w;
        }
        __syncthreads();
        #pragma unroll
        for (int k = 0; k < 16; k++) {
            float4 a4 = *(const float4*)&As[k][tr*4];
            float4 b4 = *(const float4*)&Bs[k][tc*4];
            float a[4] = {a4.x,a4.y,a4.z,a4.w};
            float b[4] = {b4.x,b4.y,b4.z,b4.w};
            #pragma unroll
            for (int i = 0; i < 4; i++)
                #pragma unroll
                for (int j = 0; j < 4; j++) acc[i][j] += a[i] * b[j];
        }
        __syncthreads();
    }
    #pragma unroll
    for (int i = 0; i < 4; i++) {
        float bv = BIAS ? ga.bias[z][m0 + tr*4 + i] : 0.0f;
        float4 v = { acc[i][0]+bv, acc[i][1]+bv, acc[i][2]+bv, acc[i][3]+bv };
        *(float4*)&Cb[(size_t)(m0+tr*4+i)*ldc + n0 + tc*4] = v;
    }
}

// ---------------- batched fp16 mma GEMM (64x64 tile, fp32 acc) ----------
// A [m][k] fp16, B [n][k] fp16. OUTMODE: 0=f32 [m][n], 1=f16 [m][n], 2=f16 [n][m].
struct HArgs {
    const __half* A[40];
    const __half* B[40];
    void*         C[40];
    const float*  bias[40];
};

template<int OUTMODE, bool BIAS>
__global__ void __launch_bounds__(256) gemm_h(
    HArgs ha, int lda, int ldb, int ldc, int K)
{
    __shared__ uint32_t As[64*12];   // [row][8 words + 4 pad]
    __shared__ uint32_t Bs[64*12];
    int tid = threadIdx.x, z = blockIdx.z;
    const __half* Ab = ha.A[z];
    const __half* Bb = ha.B[z];
    int m0 = blockIdx.y * 64, n0 = blockIdx.x * 64;
    int lane = tid & 31, wid = tid >> 5;
    int wmi = wid >> 2, wni = wid & 3;            // 2 x 4 warps
    int g = lane >> 2, tg = lane & 3;
    float acc[2][2][4] = {};
    int srow = tid >> 2, sq = tid & 3;            // staging: row, quarter

    for (int k0 = 0; k0 < K; k0 += 16) {
        uint2 av = *(const uint2*)(Ab + (size_t)(m0+srow)*lda + k0 + sq*4);
        uint2 bv = *(const uint2*)(Bb + (size_t)(n0+srow)*ldb + k0 + sq*4);
        __syncthreads();
        *(uint2*)&As[srow*12 + sq*2] = av;
        *(uint2*)&Bs[srow*12 + sq*2] = bv;
        __syncthreads();
        uint32_t bf[2][2];
        #pragma unroll
        for (int nt = 0; nt < 2; nt++) {
            int nr = wni*16 + nt*8 + g;
            bf[nt][0] = Bs[nr*12 + tg];
            bf[nt][1] = Bs[nr*12 + 4 + tg];
        }
        #pragma unroll
        for (int mt = 0; mt < 2; mt++) {
            int rb = wmi*32 + mt*16;
            uint32_t a0 = As[(rb + g    )*12 + tg];
            uint32_t a1 = As[(rb + 8 + g)*12 + tg];
            uint32_t a2 = As[(rb + g    )*12 + 4 + tg];
            uint32_t a3 = As[(rb + 8 + g)*12 + 4 + tg];
            #pragma unroll
            for (int nt = 0; nt < 2; nt++)
                asm volatile(
                    "mma.sync.aligned.m16n8k16.row.col.f32.f16.f16.f32 "
                    "{%0,%1,%2,%3},{%4,%5,%6,%7},{%8,%9},{%0,%1,%2,%3};\n"
                    : "+f"(acc[mt][nt][0]), "+f"(acc[mt][nt][1]),
                      "+f"(acc[mt][nt][2]), "+f"(acc[mt][nt][3])
                    : "r"(a0), "r"(a1), "r"(a2), "r"(a3),
                      "r"(bf[nt][0]), "r"(bf[nt][1]));
        }
    }

    #pragma unroll
    for (int mt = 0; mt < 2; mt++) {
        int r0 = m0 + wmi*32 + mt*16 + g;
        int r1 = r0 + 8;
        float bv0 = BIAS ? ha.bias[z][r0] : 0.0f;
        float bv1 = BIAS ? ha.bias[z][r1] : 0.0f;
        #pragma unroll
        for (int nt = 0; nt < 2; nt++) {
            int cc = n0 + wni*16 + nt*8 + tg*2;
            float v00 = acc[mt][nt][0] + bv0, v01 = acc[mt][nt][1] + bv0;
            float v10 = acc[mt][nt][2] + bv1, v11 = acc[mt][nt][3] + bv1;
            if (OUTMODE == 0) {
                float* C = (float*)ha.C[z];
                *(float2*)&C[(size_t)r0*ldc + cc] = make_float2(v00, v01);
                *(float2*)&C[(size_t)r1*ldc + cc] = make_float2(v10, v11);
            } else if (OUTMODE == 1) {
                __half* C = (__half*)ha.C[z];
                *(__half2*)&C[(size_t)r0*ldc + cc] = __floats2half2_rn(v00, v01);
                *(__half2*)&C[(size_t)r1*ldc + cc] = __floats2half2_rn(v10, v11);
            } else {
                __half* C = (__half*)ha.C[z];
                C[(size_t)(cc  )*ldc + r0] = __float2half(v00);
                C[(size_t)(cc+1)*ldc + r0] = __float2half(v01);
                C[(size_t)(cc  )*ldc + r1] = __float2half(v10);
                C[(size_t)(cc+1)*ldc + r1] = __float2half(v11);
            }
        }
    }
}

// ---------------- softmax over rows of 256 (fp32 in, fp32+fp16 out) -----
__global__ void softmax_kernel()
{
    float* row = g_S + (size_t)blockIdx.x * 256;
    __half* row16 = g_S16 + (size_t)blockIdx.x * 256;
    int tid = threadIdx.x;
    float v = row[tid];
    __shared__ float red[8];
    float mx = v;
    #pragma unroll
    for (int o = 16; o; o >>= 1) mx = fmaxf(mx, __shfl_xor_sync(0xffffffffu, mx, o));
    if ((tid & 31) == 0) red[tid >> 5] = mx;
    __syncthreads();
    float bmax = red[0];
    #pragma unroll
    for (int i = 1; i < 8; i++) bmax = fmaxf(bmax, red[i]);
    float e = __expf(v - bmax);
    float s = e;
    #pragma unroll
    for (int o = 16; o; o >>= 1) s += __shfl_xor_sync(0xffffffffu, s, o);
    __syncthreads();
    if ((tid & 31) == 0) red[tid >> 5] = s;
    __syncthreads();
    float bsum = red[0];
    #pragma unroll
    for (int i = 1; i < 8; i++) bsum += red[i];
    row16[tid] = __float2half(e / bsum);
}

// ---------------- bfold (parallel) ----------------
__global__ void bfold_kernel(const float* __restrict__ wm,
                             const float* __restrict__ bz,
                             const float* __restrict__ bm)
{
    int r = blockIdx.x, t = threadIdx.x;
    float s = wm[(size_t)r*768 + t] * bz[t]
            + wm[(size_t)r*768 + 256 + t] * bz[256 + t];
    __shared__ float red[8];
    #pragma unroll
    for (int o = 16; o; o >>= 1) s += __shfl_xor_sync(0xffffffffu, s, o);
    if ((t & 31) == 0) red[t >> 5] = s;
    __syncthreads();
    if (t == 0) {
        float tot = bm[r];
        #pragma unroll
        for (int i = 0; i < 8; i++) tot += red[i];
        g_bf[r] = tot;
    }
}

// ======== fused big GEMM (fp16 mma.m16n8k16) + bilinear G + gating ========
__global__ void __launch_bounds__(512) fused_f16_gate(float* __restrict__ out)
{
    __shared__ uint32_t sm[12032];
    int tid = threadIdx.x, lane = tid & 31, wid = tid >> 5;
    int y  = blockIdx.x;
    int m0 = blockIdx.y * 64;
    int b  = blockIdx.z;
    int wmi = wid >> 2, wni = wid & 3;           // 4 x 4
    int g = lane >> 2, tg = lane & 3;

    const __half* Xb = g_h16 + (size_t)b * 256 * HW_ + (size_t)y * 128;
    bool doB = tid < 256;
    int kkp = (tid & 255) >> 4, px8 = tid & 15;

    float acc[3][4][4];
    #pragma unroll
    for (int s = 0; s < 3; s++)
        #pragma unroll
        for (int n = 0; n < 4; n++)
            #pragma unroll
            for (int c = 0; c < 4; c++) acc[s][n][c] = 0.0f;

    uint4 va0, va1, blo, bhi;

    int r0s = tid >> 2,         q0 = tid & 3;
    int r1s = (512 + tid) >> 2, q1 = tid & 3;
    int grow0 = (r0s >> 6) * 256 + m0 + (r0s & 63);
    int grow1 = (r1s >> 6) * 256 + m0 + (r1s & 63);

    va0 = *(const uint4*)(g_w16 + (size_t)grow0*256 + q0*8);
    if (doB) {
        va1 = *(const uint4*)(g_w16 + (size_t)grow1*256 + q1*8);
        blo = *(const uint4*)(Xb + (size_t)(2*kkp  ) * HW_ + px8*8);
        bhi = *(const uint4*)(Xb + (size_t)(2*kkp+1) * HW_ + px8*8);
    }
    {
        *(uint4*)&sm[r0s*20 + q0*4] = va0;
        if (doB) {
            *(uint4*)&sm[r1s*20 + q1*4] = va1;
            const unsigned short* lp = (const unsigned short*)&blo;
            const unsigned short* hp = (const unsigned short*)&bhi;
            #pragma unroll
            for (int j = 0; j < 8; j++)
                sm[7680 + (px8*8 + j)*17 + kkp] = (uint32_t)lp[j] | ((uint32_t)hp[j] << 16);
        }
    }
    __syncthreads();

    for (int c = 0; c < 8; c++) {
        if (c < 7) {
            int k0 = 32*(c+1);
            va0 = *(const uint4*)(g_w16 + (size_t)grow0*256 + k0 + q0*8);
            if (doB) {
                va1 = *(const uint4*)(g_w16 + (size_t)grow1*256 + k0 + q1*8);
                blo = *(const uint4*)(Xb + (size_t)(k0 + 2*kkp  ) * HW_ + px8*8);
                bhi = *(const uint4*)(Xb + (size_t)(k0 + 2*kkp+1) * HW_ + px8*8);
            }
        }
        {
            uint32_t* A  = sm + (c & 1) * 3840;
            uint32_t* Bv = sm + 7680 + (c & 1) * 2176;
            #pragma unroll
            for (int ks = 0; ks < 2; ks++) {
                uint32_t bfr[4][2];
                #pragma unroll
                for (int nt = 0; nt < 4; nt++) {
                    int w = (wni*32 + nt*8 + g)*17 + ks*8 + tg;
                    bfr[nt][0] = Bv[w];
                    bfr[nt][1] = Bv[w + 4];
                }
                #pragma unroll
                for (int s = 0; s < 3; s++) {
                    int rb = s*64 + wmi*16;
                    uint32_t a0 = A[(rb + g    )*20 + ks*8 + tg    ];
                    uint32_t a1 = A[(rb + 8 + g)*20 + ks*8 + tg    ];
                    uint32_t a2 = A[(rb + g    )*20 + ks*8 + tg + 4];
                    uint32_t a3 = A[(rb + 8 + g)*20 + ks*8 + tg + 4];
                    #pragma unroll
                    for (int nt = 0; nt < 4; nt++)
                        asm volatile(
                            "mma.sync.aligned.m16n8k16.row.col.f32.f16.f16.f32 "
                            "{%0,%1,%2,%3},{%4,%5,%6,%7},{%8,%9},{%0,%1,%2,%3};\n"
                            : "+f"(acc[s][nt][0]), "+f"(acc[s][nt][1]),
                              "+f"(acc[s][nt][2]), "+f"(acc[s][nt][3])
                            : "r"(a0), "r"(a1), "r"(a2), "r"(a3),
                              "r"(bfr[nt][0]), "r"(bfr[nt][1]));
                }
            }
        }
        if (c < 7) {
            int nb = (c + 1) & 1;
            uint32_t* A  = sm + nb * 3840;
            uint32_t* Bv = sm + 7680 + nb * 2176;
            *(uint4*)&A[r0s*20 + q0*4] = va0;
            if (doB) {
                *(uint4*)&A[r1s*20 + q1*4] = va1;
                const unsigned short* lp = (const unsigned short*)&blo;
                const unsigned short* hp = (const unsigned short*)&bhi;
                #pragma unroll
                for (int j = 0; j < 8; j++)
                    Bv[(px8*8 + j)*17 + kkp] = (uint32_t)lp[j] | ((uint32_t)hp[j] << 16);
            }
        }
        __syncthreads();
    }

    // ---- gy: y-interp of G rows (192 x 16) into smem ----
    float* gy = (float*)sm;
    float sy = (y + 0.5f) * 0.125f - 0.5f; if (sy < 0.0f) sy = 0.0f;
    int y0 = (int)sy; float fy = sy - (float)y0; int y1 = min(y0 + 1, 15);
    #pragma unroll
    for (int i = 0; i < 6; i++) {
        int idx = tid + 512*i;
        int r = idx >> 4, px16 = idx & 15;
        int grow = (r >> 6) * 256 + m0 + (r & 63);
        const float* Gb = g_G + ((size_t)b*768 + grow) * 256;
        gy[r*16 + px16] = (1.0f - fy) * Gb[y0*16 + px16] + fy * Gb[y1*16 + px16];
    }
    __syncthreads();

    // ---- gating epilogue (m read as fp16, fast transcendentals) ----
    const size_t OUT2 = (size_t)B_ * 256 * HW_;
    #pragma unroll
    for (int rr = 0; rr < 2; rr++) {
        int o_loc  = wmi*16 + g + rr*8;
        int o_glob = m0 + o_loc;
        float bv0 = g_bf[o_glob];
        float bv1 = g_bf[256 + o_glob];
        float bv2 = g_bf[512 + o_glob];
        const __half* mrow = g_m16 + ((size_t)b*256 + o_glob)*HW_ + (size_t)y*128;
        float* hrow = out + ((size_t)b*256 + o_glob)*HW_ + (size_t)y*128;
        float* mrow_out = hrow + OUT2;
        #pragma unroll
        for (int nt = 0; nt < 4; nt++) {
            int x = wni*32 + nt*8 + tg*2;
            __half2 mh = *(const __half2*)&mrow[x];
            float2 mv = __half22float2(mh);
            float nh[2], nm[2];
            #pragma unroll
            for (int px = 0; px < 2; px++) {
                int xx = x + px;
                float sx = (xx + 0.5f) * 0.125f - 0.5f; if (sx < 0.0f) sx = 0.0f;
                int x0 = (int)sx; float fx = sx - (float)x0; int x1 = min(x0 + 1, 15);
                float g0 = (1.0f-fx)*gy[(0*64+o_loc)*16 + x0] + fx*gy[(0*64+o_loc)*16 + x1];
                float g1 = (1.0f-fx)*gy[(1*64+o_loc)*16 + x0] + fx*gy[(1*64+o_loc)*16 + x1];
                float g2 = (1.0f-fx)*gy[(2*64+o_loc)*16 + x0] + fx*gy[(2*64+o_loc)*16 + x1];
                int cc = rr*2 + px;
                float mo = acc[0][nt][cc] + bv0 + g0;
                float mg = acc[1][nt][cc] + bv1 + g1;
                float mi = acc[2][nt][cc] + bv2 + g2;
                float mval = px ? mv.y : mv.x;
                float gi = fast_sig(mi);
                float nmv = (1.0f - gi) * mval + gi * fast_tanh(mg);
                nm[px] = nmv;
                nh[px] = nmv * fast_sig(mo);
            }
            *(float2*)&hrow[x]     = make_float2(nh[0], nh[1]);
            *(float2*)&mrow_out[x] = make_float2(nm[0], nm[1]);
        }
    }
}

// ---------------- launcher ----------------
extern "C" void kernel_launch(void* const* d_in, const int* in_sizes, int n_in,
                              void* d_out, int out_size)
{
    const float* h   = (const float*)d_in[0];
    const float* m   = (const float*)d_in[1];
    const float* wq  = (const float*)d_in[2];
    const float* bq  = (const float*)d_in[3];
    const float* wk  = (const float*)d_in[4];
    const float* bk  = (const float*)d_in[5];
    const float* wv  = (const float*)d_in[6];
    const float* bv  = (const float*)d_in[7];
    const float* wkm = (const float*)d_in[8];
    const float* bkm = (const float*)d_in[9];
    const float* wvm = (const float*)d_in[10];
    const float* bvm = (const float*)d_in[11];
    const float* wz  = (const float*)d_in[12];
    const float* bz  = (const float*)d_in[13];
    const float* wm  = (const float*)d_in[14];
    const float* bm  = (const float*)d_in[15];
    float* out = (float*)d_out;

    float *S, *ZT, *G, *Wzz;
    __half *HpT, *MpT, *W516, *QT, *KT, *KmT, *V, *Vm, *S16;
    cudaGetSymbolAddress((void**)&S,    g_S);
    cudaGetSymbolAddress((void**)&S16,  g_S16);
    cudaGetSymbolAddress((void**)&ZT,   g_ZT);
    cudaGetSymbolAddress((void**)&G,    g_G);
    cudaGetSymbolAddress((void**)&Wzz,  g_Wzz);
    cudaGetSymbolAddress((void**)&HpT,  g_HpT);
    cudaGetSymbolAddress((void**)&MpT,  g_MpT);
    cudaGetSymbolAddress((void**)&W516, g_W516);
    cudaGetSymbolAddress((void**)&QT,   g_QT);
    cudaGetSymbolAddress((void**)&KT,   g_KT);
    cudaGetSymbolAddress((void**)&KmT,  g_KmT);
    cudaGetSymbolAddress((void**)&V,    g_V);
    cudaGetSymbolAddress((void**)&Vm,   g_Vm);

    // 1) pooling (+ h16/m16 + transposed pooled fp16) and weight prep
    pool_kernel<<<dim3(8192, 2), 256>>>(h, m);
    w16_kernel<<<768, 256>>>(wm);
    w5_kernel<<<dim3(256, 5), 256>>>(wq, wk, wv, wkm, wvm);

    // 2) folded weights / bias
    {
        GArgs ga = {};
        ga.A[0] = wm; ga.B[0] = wz; ga.C[0] = Wzz;
        gemm_b<false,false,false><<<dim3(8,12,1), 256>>>(ga, 768, 512, 512, 512);
    }
    bfold_kernel<<<768, 256>>>(wm, bz, bm);

    // 3a) projections with TRANSPOSED fp16 output: Q^T, K^T, Km^T
    {
        HArgs ha = {};
        const __half* W3[3] = { W516 + 0*65536, W516 + 1*65536, W516 + 3*65536 }; // wq, wk, wkm
        const float*  b3[3] = { bq, bk, bkm };
        __half* C3[3] = { QT, KT, KmT };
        for (int s = 0; s < 3; s++)
            for (int bt = 0; bt < 8; bt++) {
                int z = s*8 + bt;
                ha.A[z] = W3[s];
                ha.B[z] = (s < 2 ? HpT : MpT) + bt*PB;
                ha.C[z] = C3[s] + bt*PB;
                ha.bias[z] = b3[s];
            }
        gemm_h<2,true><<<dim3(4,4,24), 256>>>(ha, 256, 256, 256, 256);
    }
    // 3b) projections with normal fp16 output: V, Vm
    {
        HArgs ha = {};
        const __half* W2[2] = { W516 + 2*65536, W516 + 4*65536 };  // wv, wvm
        const float*  b2[2] = { bv, bvm };
        __half* C2[2] = { V, Vm };
        for (int s = 0; s < 2; s++)
            for (int bt = 0; bt < 8; bt++) {
                int z = s*8 + bt;
                ha.A[z] = W2[s];
                ha.B[z] = (s == 0 ? HpT : MpT) + bt*PB;
                ha.C[z] = C2[s] + bt*PB;
                ha.bias[z] = b2[s];
            }
        gemm_h<1,true><<<dim3(4,4,16), 256>>>(ha, 256, 256, 256, 256);
    }

    // 4) scores: S[p,q] = Q^T[p,:] . K^T[q,:]  (fp32 out)
    {
        HArgs ha = {};
        for (int z = 0; z < 16; z++) {
            int bt = z & 7;
            ha.A[z] = QT + bt*PB;
            ha.B[z] = ((z < 8) ? KT : KmT) + bt*PB;
            ha.C[z] = S + (long long)z*PB;
        }
        gemm_h<0,false><<<dim3(4,4,16), 256>>>(ha, 256, 256, 256, 256);
    }

    // 5) softmax -> S16
    softmax_kernel<<<4096, 256>>>();

    // 6) ZT[d,p] = V[d,:] . S16[p,:]  (fp32 out)
    {
        HArgs ha = {};
        for (int z = 0; z < 16; z++) {
            int bt = z & 7;
            ha.A[z] = ((z < 8) ? V : Vm) + bt*PB;
            ha.B[z] = S16 + (long long)z*PB;
            ha.C[z] = ZT + bt*2*PB + ((z < 8) ? 0 : PB);
        }
        gemm_h<0,false><<<dim3(4,4,16), 256>>>(ha, 256, 256, 256, 256);
    }

    // 7) G = Wzz @ ZTcat (fp32)
    {
        GArgs ga = {};
        for (int bt = 0; bt < 8; bt++) {
            ga.A[bt] = Wzz;
            ga.B[bt] = ZT + bt*2*PB;
            ga.C[bt] = G + (long long)bt*768*256;
        }
        gemm_b<false,false,false><<<dim3(4,12,8), 256>>>(ga, 512, 256, 256, 512);
    }

    // 8) fused fp16-mma GEMM + upsample + gating -> outputs
    fused_f16_gate<<<dim3(128, 4, 8), 512>>>(out);
}

// round 12
// speedup vs baseline: 1.6716x; 1.0963x over previous
#include <cuda_runtime.h>
#include <cuda_fp16.h>
#include <cstdint>

#define B_   8
#define HW_  16384
#define PB   (256LL*256LL)

// ---------------- scratch ----------------
__device__ float  g_S [2*B_*256*256];         // scores fp32 (pre-softmax)
__device__ __half g_S16[2*B_*256*256];        // softmax probs fp16
__device__ __half g_ZTT[B_*256*512];          // Z^T fp16 [b][p][c:512] (h 0-255, m 256-511)
__device__ float  g_G [B_*768*256];           // Wzz @ Zcat on 16x16 grid (fp32)
__device__ __half g_Wzz16[768*512];           // folded weight fp16
__device__ __half g_wzT16[512*512];           // wz transposed fp16  [c][o]
__device__ __half g_wma16[768*512];           // wm[:, :512] fp16
__device__ float  g_bf[768];
__device__ __half g_h16[(size_t)B_*256*HW_]; // fp16 h (64 MiB)
__device__ __half g_m16[(size_t)B_*256*HW_]; // fp16 m (64 MiB)
__device__ __half g_w16[768*256];            // fp16 wm[:,512:768]
__device__ __half g_W516[5*256*256];         // fp16 {wq,wk,wv,wkm,wvm}
__device__ __half g_HpT[B_*256*256];         // pooled h, transposed [b][p][c]
__device__ __half g_MpT[B_*256*256];         // pooled m, transposed [b][p][c]
__device__ __half g_QT [B_*256*256];         // Q^T  [b][p][d]
__device__ __half g_KT [B_*256*256];         // K^T  [b][q][d]
__device__ __half g_KmT[B_*256*256];         // Km^T [b][q][d]
__device__ __half g_V  [B_*256*256];         // V    [b][d][p]
__device__ __half g_Vm [B_*256*256];         // Vm   [b][d][p]

__device__ __forceinline__ float fast_tanh(float x) {
    float r; asm("tanh.approx.f32 %0, %1;" : "=f"(r) : "f"(x)); return r;
}
__device__ __forceinline__ float fast_sig(float x) {
    return 1.0f / (1.0f + __expf(-x));
}

// ---------------- pooling: MLP-4 + fp16 emit + transposed pooled --------
__global__ void pool_kernel(const float* __restrict__ h, const float* __restrict__ m)
{
    int tid = threadIdx.x;
    int hw = tid >> 4, l16 = tid & 15;
    const float* src = blockIdx.y ? m : h;
    __half* d16  = blockIdx.y ? g_m16 : g_h16;
    __half* dstT = blockIdx.y ? g_MpT : g_HpT;
    int gh = blockIdx.x * 16 + hw;
    int s0 = gh * 4;

    float4 v[4];
    #pragma unroll
    for (int j = 0; j < 4; j++)
        v[j] = *(const float4*)(src + (size_t)(s0 + j) * 64 + l16 * 4);

    #pragma unroll
    for (int j = 0; j < 4; j++) {
        __half2 p0 = __floats2half2_rn(v[j].x, v[j].y);
        __half2 p1 = __floats2half2_rn(v[j].z, v[j].w);
        uint2 u;
        u.x = *(const uint32_t*)&p0;
        u.y = *(const uint32_t*)&p1;
        *(uint2*)(d16 + (size_t)(s0 + j) * 64 + l16 * 4) = u;
    }

    #pragma unroll
    for (int j = 0; j < 4; j++) {
        float s = v[j].x + v[j].y + v[j].z + v[j].w;
        #pragma unroll
        for (int o = 8; o; o >>= 1) s += __shfl_xor_sync(0xffffffffu, s, o);
        if (l16 == 0) {
            int idx = s0 + j;   // (b*256 + c)*256 + p
            int off = (idx & 0xFF0000) | ((idx & 255) << 8) | ((idx >> 8) & 255);
            dstT[off] = __float2half(s * (1.0f / 64.0f));
        }
    }
}

// ---------------- weight fp16 preps ----------------
__global__ void w16_kernel(const float* __restrict__ wm)
{
    int r = blockIdx.x, k = threadIdx.x;
    g_w16[r*256 + k] = __float2half(wm[(size_t)r*768 + 512 + k]);
}

__global__ void w5_kernel(const float* __restrict__ w0, const float* __restrict__ w1,
                          const float* __restrict__ w2, const float* __restrict__ w3,
                          const float* __restrict__ w4)
{
    int idx = blockIdx.x * 256 + threadIdx.x;
    const float* w;
    switch (blockIdx.y) {
        case 0: w = w0; break;
        case 1: w = w1; break;
        case 2: w = w2; break;
        case 3: w = w3; break;
        default: w = w4; break;
    }
    g_W516[blockIdx.y * 65536 + idx] = __float2half(w[idx]);
}

// wma16[r][o] = wm[r*768+o] (o<512); wzT16[c][o] = wz[o*512+c]
__global__ void wma_kernel(const float* __restrict__ wm)
{
    int r = blockIdx.x, o = threadIdx.x;
    g_wma16[r*512 + o] = __float2half(wm[(size_t)r*768 + o]);
}
__global__ void wzT_kernel(const float* __restrict__ wz)
{
    int c = blockIdx.x, o = threadIdx.x;
    g_wzT16[c*512 + o] = __float2half(wz[(size_t)o*512 + c]);
}

// ---------------- batched fp16 mma GEMM (64x64 tile, fp32 acc) ----------
// A [m][k] fp16, B [n][k] fp16. OUTMODE: 0=f32 [m][n], 1=f16 [m][n], 2=f16 [n][m].
struct HArgs {
    const __half* A[40];
    const __half* B[40];
    void*         C[40];
    const float*  bias[40];
};

template<int OUTMODE, bool BIAS>
__global__ void __launch_bounds__(256) gemm_h(
    HArgs ha, int lda, int ldb, int ldc, int K)
{
    __shared__ uint32_t As[64*12];   // [row][8 words + 4 pad]
    __shared__ uint32_t Bs[64*12];
    int tid = threadIdx.x, z = blockIdx.z;
    const __half* Ab = ha.A[z];
    const __half* Bb = ha.B[z];
    int m0 = blockIdx.y * 64, n0 = blockIdx.x * 64;
    int lane = tid & 31, wid = tid >> 5;
    int wmi = wid >> 2, wni = wid & 3;            // 2 x 4 warps
    int g = lane >> 2, tg = lane & 3;
    float acc[2][2][4] = {};
    int srow = tid >> 2, sq = tid & 3;

    for (int k0 = 0; k0 < K; k0 += 16) {
        uint2 av = *(const uint2*)(Ab + (size_t)(m0+srow)*lda + k0 + sq*4);
        uint2 bv = *(const uint2*)(Bb + (size_t)(n0+srow)*ldb + k0 + sq*4);
        __syncthreads();
        *(uint2*)&As[srow*12 + sq*2] = av;
        *(uint2*)&Bs[srow*12 + sq*2] = bv;
        __syncthreads();
        uint32_t bf[2][2];
        #pragma unroll
        for (int nt = 0; nt < 2; nt++) {
            int nr = wni*16 + nt*8 + g;
            bf[nt][0] = Bs[nr*12 + tg];
            bf[nt][1] = Bs[nr*12 + 4 + tg];
        }
        #pragma unroll
        for (int mt = 0; mt < 2; mt++) {
            int rb = wmi*32 + mt*16;
            uint32_t a0 = As[(rb + g    )*12 + tg];
            uint32_t a1 = As[(rb + 8 + g)*12 + tg];
            uint32_t a2 = As[(rb + g    )*12 + 4 + tg];
            uint32_t a3 = As[(rb + 8 + g)*12 + 4 + tg];
            #pragma unroll
            for (int nt = 0; nt < 2; nt++)
                asm volatile(
                    "mma.sync.aligned.m16n8k16.row.col.f32.f16.f16.f32 "
                    "{%0,%1,%2,%3},{%4,%5,%6,%7},{%8,%9},{%0,%1,%2,%3};\n"
                    : "+f"(acc[mt][nt][0]), "+f"(acc[mt][nt][1]),
                      "+f"(acc[mt][nt][2]), "+f"(acc[mt][nt][3])
                    : "r"(a0), "r"(a1), "r"(a2), "r"(a3),
                      "r"(bf[nt][0]), "r"(bf[nt][1]));
        }
    }

    #pragma unroll
    for (int mt = 0; mt < 2; mt++) {
        int r0 = m0 + wmi*32 + mt*16 + g;
        int r1 = r0 + 8;
        float bv0 = BIAS ? ha.bias[z][r0] : 0.0f;
        float bv1 = BIAS ? ha.bias[z][r1] : 0.0f;
        #pragma unroll
        for (int nt = 0; nt < 2; nt++) {
            int cc = n0 + wni*16 + nt*8 + tg*2;
            float v00 = acc[mt][nt][0] + bv0, v01 = acc[mt][nt][1] + bv0;
            float v10 = acc[mt][nt][2] + bv1, v11 = acc[mt][nt][3] + bv1;
            if (OUTMODE == 0) {
                float* C = (float*)ha.C[z];
                *(float2*)&C[(size_t)r0*ldc + cc] = make_float2(v00, v01);
                *(float2*)&C[(size_t)r1*ldc + cc] = make_float2(v10, v11);
            } else if (OUTMODE == 1) {
                __half* C = (__half*)ha.C[z];
                *(__half2*)&C[(size_t)r0*ldc + cc] = __floats2half2_rn(v00, v01);
                *(__half2*)&C[(size_t)r1*ldc + cc] = __floats2half2_rn(v10, v11);
            } else {
                __half* C = (__half*)ha.C[z];
                C[(size_t)(cc  )*ldc + r0] = __float2half(v00);
                C[(size_t)(cc+1)*ldc + r0] = __float2half(v01);
                C[(size_t)(cc  )*ldc + r1] = __float2half(v10);
                C[(size_t)(cc+1)*ldc + r1] = __float2half(v11);
            }
        }
    }
}

// ---------------- softmax: warp per row of 256 ----------------
__global__ void softmax_kernel()   // grid 512, block 256 -> 8 rows/block
{
    int warp = threadIdx.x >> 5, lane = threadIdx.x & 31;
    size_t row = (size_t)blockIdx.x * 8 + warp;
    const float* rp = g_S + row * 256;
    float4 v0 = ((const float4*)rp)[lane*2];
    float4 v1 = ((const float4*)rp)[lane*2 + 1];
    float mx = fmaxf(fmaxf(fmaxf(v0.x, v0.y), fmaxf(v0.z, v0.w)),
                     fmaxf(fmaxf(v1.x, v1.y), fmaxf(v1.z, v1.w)));
    #pragma unroll
    for (int o = 16; o; o >>= 1) mx = fmaxf(mx, __shfl_xor_sync(0xffffffffu, mx, o));
    float e[8];
    e[0] = __expf(v0.x - mx); e[1] = __expf(v0.y - mx);
    e[2] = __expf(v0.z - mx); e[3] = __expf(v0.w - mx);
    e[4] = __expf(v1.x - mx); e[5] = __expf(v1.y - mx);
    e[6] = __expf(v1.z - mx); e[7] = __expf(v1.w - mx);
    float s = e[0]+e[1]+e[2]+e[3]+e[4]+e[5]+e[6]+e[7];
    #pragma unroll
    for (int o = 16; o; o >>= 1) s += __shfl_xor_sync(0xffffffffu, s, o);
    float inv = 1.0f / s;
    __half2 h0 = __floats2half2_rn(e[0]*inv, e[1]*inv);
    __half2 h1 = __floats2half2_rn(e[2]*inv, e[3]*inv);
    __half2 h2 = __floats2half2_rn(e[4]*inv, e[5]*inv);
    __half2 h3 = __floats2half2_rn(e[6]*inv, e[7]*inv);
    uint4 u = { *(uint32_t*)&h0, *(uint32_t*)&h1, *(uint32_t*)&h2, *(uint32_t*)&h3 };
    *(uint4*)(g_S16 + row * 256 + lane * 8) = u;
}

// ---------------- bfold (parallel) ----------------
__global__ void bfold_kernel(const float* __restrict__ wm,
                             const float* __restrict__ bz,
                             const float* __restrict__ bm)
{
    int r = blockIdx.x, t = threadIdx.x;
    float s = wm[(size_t)r*768 + t] * bz[t]
            + wm[(size_t)r*768 + 256 + t] * bz[256 + t];
    __shared__ float red[8];
    #pragma unroll
    for (int o = 16; o; o >>= 1) s += __shfl_xor_sync(0xffffffffu, s, o);
    if ((t & 31) == 0) red[t >> 5] = s;
    __syncthreads();
    if (t == 0) {
        float tot = bm[r];
        #pragma unroll
        for (int i = 0; i < 8; i++) tot += red[i];
        g_bf[r] = tot;
    }
}

// ======== fused big GEMM (fp16 mma.m16n8k16) + bilinear G + gating ========
__global__ void __launch_bounds__(512) fused_f16_gate(float* __restrict__ out)
{
    __shared__ uint32_t sm[12032];
    int tid = threadIdx.x, lane = tid & 31, wid = tid >> 5;
    int y  = blockIdx.x;
    int m0 = blockIdx.y * 64;
    int b  = blockIdx.z;
    int wmi = wid >> 2, wni = wid & 3;           // 4 x 4
    int g = lane >> 2, tg = lane & 3;

    const __half* Xb = g_h16 + (size_t)b * 256 * HW_ + (size_t)y * 128;
    bool doB = tid < 256;
    int kkp = (tid & 255) >> 4, px8 = tid & 15;

    float acc[3][4][4];
    #pragma unroll
    for (int s = 0; s < 3; s++)
        #pragma unroll
        for (int n = 0; n < 4; n++)
            #pragma unroll
            for (int c = 0; c < 4; c++) acc[s][n][c] = 0.0f;

    uint4 va0, va1, blo, bhi;

    int r0s = tid >> 2,         q0 = tid & 3;
    int r1s = (512 + tid) >> 2, q1 = tid & 3;
    int grow0 = (r0s >> 6) * 256 + m0 + (r0s & 63);
    int grow1 = (r1s >> 6) * 256 + m0 + (r1s & 63);

    va0 = *(const uint4*)(g_w16 + (size_t)grow0*256 + q0*8);
    if (doB) {
        va1 = *(const uint4*)(g_w16 + (size_t)grow1*256 + q1*8);
        blo = *(const uint4*)(Xb + (size_t)(2*kkp  ) * HW_ + px8*8);
        bhi = *(const uint4*)(Xb + (size_t)(2*kkp+1) * HW_ + px8*8);
    }
    {
        *(uint4*)&sm[r0s*20 + q0*4] = va0;
        if (doB) {
            *(uint4*)&sm[r1s*20 + q1*4] = va1;
            const unsigned short* lp = (const unsigned short*)&blo;
            const unsigned short* hp = (const unsigned short*)&bhi;
            #pragma unroll
            for (int j = 0; j < 8; j++)
                sm[7680 + (px8*8 + j)*17 + kkp] = (uint32_t)lp[j] | ((uint32_t)hp[j] << 16);
        }
    }
    __syncthreads();

    for (int c = 0; c < 8; c++) {
        if (c < 7) {
            int k0 = 32*(c+1);
            va0 = *(const uint4*)(g_w16 + (size_t)grow0*256 + k0 + q0*8);
            if (doB) {
                va1 = *(const uint4*)(g_w16 + (size_t)grow1*256 + k0 + q1*8);
                blo = *(const uint4*)(Xb + (size_t)(k0 + 2*kkp  ) * HW_ + px8*8);
                bhi = *(const uint4*)(Xb + (size_t)(k0 + 2*kkp+1) * HW_ + px8*8);
            }
        }
        {
            uint32_t* A  = sm + (c & 1) * 3840;
            uint32_t* Bv = sm + 7680 + (c & 1) * 2176;
            #pragma unroll
            for (int ks = 0; ks < 2; ks++) {
                uint32_t bfr[4][2];
                #pragma unroll
                for (int nt = 0; nt < 4; nt++) {
                    int w = (wni*32 + nt*8 + g)*17 + ks*8 + tg;
                    bfr[nt][0] = Bv[w];
                    bfr[nt][1] = Bv[w + 4];
                }
                #pragma unroll
                for (int s = 0; s < 3; s++) {
                    int rb = s*64 + wmi*16;
                    uint32_t a0 = A[(rb + g    )*20 + ks*8 + tg    ];
                    uint32_t a1 = A[(rb + 8 + g)*20 + ks*8 + tg    ];
                    uint32_t a2 = A[(rb + g    )*20 + ks*8 + tg + 4];
                    uint32_t a3 = A[(rb + 8 + g)*20 + ks*8 + tg + 4];
                    #pragma unroll
                    for (int nt = 0; nt < 4; nt++)
                        asm volatile(
                            "mma.sync.aligned.m16n8k16.row.col.f32.f16.f16.f32 "
                            "{%0,%1,%2,%3},{%4,%5,%6,%7},{%8,%9},{%0,%1,%2,%3};\n"
                            : "+f"(acc[s][nt][0]), "+f"(acc[s][nt][1]),
                              "+f"(acc[s][nt][2]), "+f"(acc[s][nt][3])
                            : "r"(a0), "r"(a1), "r"(a2), "r"(a3),
                              "r"(bfr[nt][0]), "r"(bfr[nt][1]));
                }
            }
        }
        if (c < 7) {
            int nb = (c + 1) & 1;
            uint32_t* A  = sm + nb * 3840;
            uint32_t* Bv = sm + 7680 + nb * 2176;
            *(uint4*)&A[r0s*20 + q0*4] = va0;
            if (doB) {
                *(uint4*)&A[r1s*20 + q1*4] = va1;
                const unsigned short* lp = (const unsigned short*)&blo;
                const unsigned short* hp = (const unsigned short*)&bhi;
                #pragma unroll
                for (int j = 0; j < 8; j++)
                    Bv[(px8*8 + j)*17 + kkp] = (uint32_t)lp[j] | ((uint32_t)hp[j] << 16);
            }
        }
        __syncthreads();
    }

    // ---- gy: y-interp of G rows (192 x 16) into smem ----
    float* gy = (float*)sm;
    float sy = (y + 0.5f) * 0.125f - 0.5f; if (sy < 0.0f) sy = 0.0f;
    int y0 = (int)sy; float fy = sy - (float)y0; int y1 = min(y0 + 1, 15);
    #pragma unroll
    for (int i = 0; i < 6; i++) {
        int idx = tid + 512*i;
        int r = idx >> 4, px16 = idx & 15;
        int grow = (r >> 6) * 256 + m0 + (r & 63);
        const float* Gb = g_G + ((size_t)b*768 + grow) * 256;
        gy[r*16 + px16] = (1.0f - fy) * Gb[y0*16 + px16] + fy * Gb[y1*16 + px16];
    }
    __syncthreads();

    // ---- gating epilogue ----
    const size_t OUT2 = (size_t)B_ * 256 * HW_;
    #pragma unroll
    for (int rr = 0; rr < 2; rr++) {
        int o_loc  = wmi*16 + g + rr*8;
        int o_glob = m0 + o_loc;
        float bv0 = g_bf[o_glob];
        float bv1 = g_bf[256 + o_glob];
        float bv2 = g_bf[512 + o_glob];
        const __half* mrow = g_m16 + ((size_t)b*256 + o_glob)*HW_ + (size_t)y*128;
        float* hrow = out + ((size_t)b*256 + o_glob)*HW_ + (size_t)y*128;
        float* mrow_out = hrow + OUT2;
        #pragma unroll
        for (int nt = 0; nt < 4; nt++) {
            int x = wni*32 + nt*8 + tg*2;
            __half2 mh = *(const __half2*)&mrow[x];
            float2 mv = __half22float2(mh);
            float nh[2], nm[2];
            #pragma unroll
            for (int px = 0; px < 2; px++) {
                int xx = x + px;
                float sx = (xx + 0.5f) * 0.125f - 0.5f; if (sx < 0.0f) sx = 0.0f;
                int x0 = (int)sx; float fx = sx - (float)x0; int x1 = min(x0 + 1, 15);
                float g0 = (1.0f-fx)*gy[(0*64+o_loc)*16 + x0] + fx*gy[(0*64+o_loc)*16 + x1];
                float g1 = (1.0f-fx)*gy[(1*64+o_loc)*16 + x0] + fx*gy[(1*64+o_loc)*16 + x1];
                float g2 = (1.0f-fx)*gy[(2*64+o_loc)*16 + x0] + fx*gy[(2*64+o_loc)*16 + x1];
                int cc = rr*2 + px;
                float mo = acc[0][nt][cc] + bv0 + g0;
                float mg = acc[1][nt][cc] + bv1 + g1;
                float mi = acc[2][nt][cc] + bv2 + g2;
                float mval = px ? mv.y : mv.x;
                float gi = fast_sig(mi);
                float nmv = (1.0f - gi) * mval + gi * fast_tanh(mg);
                nm[px] = nmv;
                nh[px] = nmv * fast_sig(mo);
            }
            *(float2*)&hrow[x]     = make_float2(nh[0], nh[1]);
            *(float2*)&mrow_out[x] = make_float2(nm[0], nm[1]);
        }
    }
}

// ---------------- launcher ----------------
extern "C" void kernel_launch(void* const* d_in, const int* in_sizes, int n_in,
                              void* d_out, int out_size)
{
    const float* h   = (const float*)d_in[0];
    const float* m   = (const float*)d_in[1];
    const float* wq  = (const float*)d_in[2];
    const float* bq  = (const float*)d_in[3];
    const float* wk  = (const float*)d_in[4];
    const float* bk  = (const float*)d_in[5];
    const float* wv  = (const float*)d_in[6];
    const float* bv  = (const float*)d_in[7];
    const float* wkm = (const float*)d_in[8];
    const float* bkm = (const float*)d_in[9];
    const float* wvm = (const float*)d_in[10];
    const float* bvm = (const float*)d_in[11];
    const float* wz  = (const float*)d_in[12];
    const float* bz  = (const float*)d_in[13];
    const float* wm  = (const float*)d_in[14];
    const float* bm  = (const float*)d_in[15];
    float* out = (float*)d_out;

    float *S, *G;
    __half *HpT, *MpT, *W516, *QT, *KT, *KmT, *V, *Vm, *S16, *ZTT, *Wzz16, *wzT16, *wma16;
    cudaGetSymbolAddress((void**)&S,     g_S);
    cudaGetSymbolAddress((void**)&S16,   g_S16);
    cudaGetSymbolAddress((void**)&ZTT,   g_ZTT);
    cudaGetSymbolAddress((void**)&G,     g_G);
    cudaGetSymbolAddress((void**)&Wzz16, g_Wzz16);
    cudaGetSymbolAddress((void**)&wzT16, g_wzT16);
    cudaGetSymbolAddress((void**)&wma16, g_wma16);
    cudaGetSymbolAddress((void**)&HpT,   g_HpT);
    cudaGetSymbolAddress((void**)&MpT,   g_MpT);
    cudaGetSymbolAddress((void**)&W516,  g_W516);
    cudaGetSymbolAddress((void**)&QT,    g_QT);
    cudaGetSymbolAddress((void**)&KT,    g_KT);
    cudaGetSymbolAddress((void**)&KmT,   g_KmT);
    cudaGetSymbolAddress((void**)&V,     g_V);
    cudaGetSymbolAddress((void**)&Vm,    g_Vm);

    // 1) pooling + weight fp16 preps
    pool_kernel<<<dim3(8192, 2), 256>>>(h, m);
    w16_kernel<<<768, 256>>>(wm);
    w5_kernel<<<dim3(256, 5), 256>>>(wq, wk, wv, wkm, wvm);
    wma_kernel<<<768, 512>>>(wm);
    wzT_kernel<<<512, 512>>>(wz);
    bfold_kernel<<<768, 256>>>(wm, bz, bm);

    // 2) Wzz fold (fp16 mma): Wzz16[r][c] = sum_o wma16[r][o] * wzT16[c][o]
    {
        HArgs ha = {};
        ha.A[0] = wma16; ha.B[0] = wzT16; ha.C[0] = Wzz16;
        gemm_h<1,false><<<dim3(8,12,1), 256>>>(ha, 512, 512, 512, 512);
    }

    // 3a) projections with TRANSPOSED fp16 output: Q^T, K^T, Km^T
    {
        HArgs ha = {};
        const __half* W3[3] = { W516 + 0*65536, W516 + 1*65536, W516 + 3*65536 };
        const float*  b3[3] = { bq, bk, bkm };
        __half* C3[3] = { QT, KT, KmT };
        for (int s = 0; s < 3; s++)
            for (int bt = 0; bt < 8; bt++) {
                int z = s*8 + bt;
                ha.A[z] = W3[s];
                ha.B[z] = (s < 2 ? HpT : MpT) + bt*PB;
                ha.C[z] = C3[s] + bt*PB;
                ha.bias[z] = b3[s];
            }
        gemm_h<2,true><<<dim3(4,4,24), 256>>>(ha, 256, 256, 256, 256);
    }
    // 3b) projections normal fp16 output: V, Vm
    {
        HArgs ha = {};
        const __half* W2[2] = { W516 + 2*65536, W516 + 4*65536 };
        const float*  b2[2] = { bv, bvm };
        __half* C2[2] = { V, Vm };
        for (int s = 0; s < 2; s++)
            for (int bt = 0; bt < 8; bt++) {
                int z = s*8 + bt;
                ha.A[z] = W2[s];
                ha.B[z] = (s == 0 ? HpT : MpT) + bt*PB;
                ha.C[z] = C2[s] + bt*PB;
                ha.bias[z] = b2[s];
            }
        gemm_h<1,true><<<dim3(4,4,16), 256>>>(ha, 256, 256, 256, 256);
    }

    // 4) scores: S[p,q] = Q^T[p,:] . K^T[q,:]  (fp32 out)
    {
        HArgs ha = {};
        for (int z = 0; z < 16; z++) {
            int bt = z & 7;
            ha.A[z] = QT + bt*PB;
            ha.B[z] = ((z < 8) ? KT : KmT) + bt*PB;
            ha.C[z] = S + (long long)z*PB;
        }
        gemm_h<0,false><<<dim3(4,4,16), 256>>>(ha, 256, 256, 256, 256);
    }

    // 5) softmax -> S16 (warp per row)
    softmax_kernel<<<512, 256>>>();

    // 6) ZTT[p][c] fp16: A=V[d][q], B=S16[p][q], transposed out (ldc=512)
    {
        HArgs ha = {};
        for (int z = 0; z < 16; z++) {
            int bt = z & 7;
            ha.A[z] = ((z < 8) ? V : Vm) + bt*PB;
            ha.B[z] = S16 + (long long)z*PB;
            ha.C[z] = ZTT + (long long)bt*256*512 + ((z < 8) ? 0 : 256);
        }
        gemm_h<2,false><<<dim3(4,4,16), 256>>>(ha, 256, 256, 512, 256);
    }

    // 7) G[r][p] = sum_c Wzz16[r][c] * ZTT[p][c]  (fp32 out, K=512)
    {
        HArgs ha = {};
        for (int bt = 0; bt < 8; bt++) {
            ha.A[bt] = Wzz16;
            ha.B[bt] = ZTT + (long long)bt*256*512;
            ha.C[bt] = G + (long long)bt*768*256;
        }
        gemm_h<0,false><<<dim3(4,12,8), 256>>>(ha, 512, 512, 256, 512);
    }

    // 8) fused fp16-mma GEMM + upsample + gating -> outputs
    fused_f16_gate<<<dim3(128, 4, 8), 512>>>(out);
}

// round 14
// speedup vs baseline: 1.7171x; 1.0272x over previous
#include <cuda_runtime.h>
#include <cuda_fp16.h>
#include <cstdint>

#define B_   8
#define HW_  16384
#define PB   (256LL*256LL)

// ---------------- scratch ----------------
__device__ float  g_S [2*B_*256*256];         // scores fp32 (pre-softmax)
__device__ __half g_S16[2*B_*256*256];        // softmax probs fp16
__device__ __half g_ZTT[B_*256*512];          // Z^T fp16 [b][p][c:512]
__device__ float  g_G [B_*768*256];           // Wzz @ Zcat on 16x16 grid (fp32)
__device__ __half g_Wzz16[768*512];
__device__ __half g_wzT16[512*512];           // wz transposed fp16 [c][o]
__device__ __half g_wma16[768*512];           // wm[:, :512] fp16
__device__ float  g_bf[768];
__device__ __half g_h16[(size_t)B_*256*HW_];
__device__ __half g_m16[(size_t)B_*256*HW_];
__device__ __half g_w16[768*256];             // wm[:,512:768] fp16
__device__ __half g_W516[5*256*256];          // {wq,wk,wv,wkm,wvm} fp16
__device__ __half g_HpT[B_*256*256];
__device__ __half g_MpT[B_*256*256];
__device__ __half g_QT [B_*256*256];
__device__ __half g_KT [B_*256*256];
__device__ __half g_KmT[B_*256*256];
__device__ __half g_V  [B_*256*256];
__device__ __half g_Vm [B_*256*256];

__device__ __forceinline__ float fast_tanh(float x) {
    float r; asm("tanh.approx.f32 %0, %1;" : "=f"(r) : "f"(x)); return r;
}
__device__ __forceinline__ float fast_sig(float x) {
    return 1.0f / (1.0f + __expf(-x));
}

// ---------------- pooling ----------------
__global__ void pool_kernel(const float* __restrict__ h, const float* __restrict__ m)
{
    int tid = threadIdx.x;
    int hw = tid >> 4, l16 = tid & 15;
    const float* src = blockIdx.y ? m : h;
    __half* d16  = blockIdx.y ? g_m16 : g_h16;
    __half* dstT = blockIdx.y ? g_MpT : g_HpT;
    int gh = blockIdx.x * 16 + hw;
    int s0 = gh * 4;

    float4 v[4];
    #pragma unroll
    for (int j = 0; j < 4; j++)
        v[j] = *(const float4*)(src + (size_t)(s0 + j) * 64 + l16 * 4);

    #pragma unroll
    for (int j = 0; j < 4; j++) {
        __half2 p0 = __floats2half2_rn(v[j].x, v[j].y);
        __half2 p1 = __floats2half2_rn(v[j].z, v[j].w);
        uint2 u;
        u.x = *(const uint32_t*)&p0;
        u.y = *(const uint32_t*)&p1;
        *(uint2*)(d16 + (size_t)(s0 + j) * 64 + l16 * 4) = u;
    }

    #pragma unroll
    for (int j = 0; j < 4; j++) {
        float s = v[j].x + v[j].y + v[j].z + v[j].w;
        #pragma unroll
        for (int o = 8; o; o >>= 1) s += __shfl_xor_sync(0xffffffffu, s, o);
        if (l16 == 0) {
            int idx = s0 + j;
            int off = (idx & 0xFF0000) | ((idx & 255) << 8) | ((idx >> 8) & 255);
            dstT[off] = __float2half(s * (1.0f / 64.0f));
        }
    }
}

// ---------------- merged fp16 weight prep ----------------
#define N1_ (768*256)
#define N2_ (5*65536)
#define N3_ (768*512)
#define N4_ (512*512)
__global__ void prep_all(const float* __restrict__ wm,
                         const float* __restrict__ w0, const float* __restrict__ w1,
                         const float* __restrict__ w2, const float* __restrict__ w3,
                         const float* __restrict__ w4,
                         const float* __restrict__ wz)
{
    int i = blockIdx.x * 1024 + threadIdx.x;
    if (i < N1_) {
        int r = i >> 8, k = i & 255;
        g_w16[i] = __float2half(wm[(size_t)r*768 + 512 + k]);
    } else if (i < N1_ + N2_) {
        int i2 = i - N1_;
        const float* w;
        switch (i2 >> 16) {
            case 0: w = w0; break;
            case 1: w = w1; break;
            case 2: w = w2; break;
            case 3: w = w3; break;
            default: w = w4; break;
        }
        g_W516[i2] = __float2half(w[i2 & 65535]);
    } else if (i < N1_ + N2_ + N3_) {
        int i3 = i - N1_ - N2_;
        int r = i3 >> 9, o = i3 & 511;
        g_wma16[i3] = __float2half(wm[(size_t)r*768 + o]);
    } else if (i < N1_ + N2_ + N3_ + N4_) {
        int i4 = i - N1_ - N2_ - N3_;
        int c = i4 >> 9, o = i4 & 511;
        g_wzT16[c*512 + o] = __float2half(wz[(size_t)o*512 + c]);
    }
}

// ---------------- batched fp16 mma GEMM (64x64 tile, fp32 acc) ----------
struct HArgs {
    const __half* A[40];
    const __half* B[40];
    void*         C[40];
    const float*  bias[40];
};

template<int OUTMODE, bool BIAS>
__global__ void __launch_bounds__(256) gemm_h(
    HArgs ha, int lda, int ldb, int ldc, int K)
{
    __shared__ uint32_t As[64*12];
    __shared__ uint32_t Bs[64*12];
    int tid = threadIdx.x, z = blockIdx.z;
    const __half* Ab = ha.A[z];
    const __half* Bb = ha.B[z];
    int m0 = blockIdx.y * 64, n0 = blockIdx.x * 64;
    int lane = tid & 31, wid = tid >> 5;
    int wmi = wid >> 2, wni = wid & 3;
    int g = lane >> 2, tg = lane & 3;
    float acc[2][2][4] = {};
    int srow = tid >> 2, sq = tid & 3;

    for (int k0 = 0; k0 < K; k0 += 16) {
        uint2 av = *(const uint2*)(Ab + (size_t)(m0+srow)*lda + k0 + sq*4);
        uint2 bv = *(const uint2*)(Bb + (size_t)(n0+srow)*ldb + k0 + sq*4);
        __syncthreads();
        *(uint2*)&As[srow*12 + sq*2] = av;
        *(uint2*)&Bs[srow*12 + sq*2] = bv;
        __syncthreads();
        uint32_t bf[2][2];
        #pragma unroll
        for (int nt = 0; nt < 2; nt++) {
            int nr = wni*16 + nt*8 + g;
            bf[nt][0] = Bs[nr*12 + tg];
            bf[nt][1] = Bs[nr*12 + 4 + tg];
        }
        #pragma unroll
        for (int mt = 0; mt < 2; mt++) {
            int rb = wmi*32 + mt*16;
            uint32_t a0 = As[(rb + g    )*12 + tg];
            uint32_t a1 = As[(rb + 8 + g)*12 + tg];
            uint32_t a2 = As[(rb + g    )*12 + 4 + tg];
            uint32_t a3 = As[(rb + 8 + g)*12 + 4 + tg];
            #pragma unroll
            for (int nt = 0; nt < 2; nt++)
                asm volatile(
                    "mma.sync.aligned.m16n8k16.row.col.f32.f16.f16.f32 "
                    "{%0,%1,%2,%3},{%4,%5,%6,%7},{%8,%9},{%0,%1,%2,%3};\n"
                    : "+f"(acc[mt][nt][0]), "+f"(acc[mt][nt][1]),
                      "+f"(acc[mt][nt][2]), "+f"(acc[mt][nt][3])
                    : "r"(a0), "r"(a1), "r"(a2), "r"(a3),
                      "r"(bf[nt][0]), "r"(bf[nt][1]));
        }
    }

    #pragma unroll
    for (int mt = 0; mt < 2; mt++) {
        int r0 = m0 + wmi*32 + mt*16 + g;
        int r1 = r0 + 8;
        float bv0 = BIAS ? ha.bias[z][r0] : 0.0f;
        float bv1 = BIAS ? ha.bias[z][r1] : 0.0f;
        #pragma unroll
        for (int nt = 0; nt < 2; nt++) {
            int cc = n0 + wni*16 + nt*8 + tg*2;
            float v00 = acc[mt][nt][0] + bv0, v01 = acc[mt][nt][1] + bv0;
            float v10 = acc[mt][nt][2] + bv1, v11 = acc[mt][nt][3] + bv1;
            if (OUTMODE == 0) {
                float* C = (float*)ha.C[z];
                *(float2*)&C[(size_t)r0*ldc + cc] = make_float2(v00, v01);
                *(float2*)&C[(size_t)r1*ldc + cc] = make_float2(v10, v11);
            } else if (OUTMODE == 1) {
                __half* C = (__half*)ha.C[z];
                *(__half2*)&C[(size_t)r0*ldc + cc] = __floats2half2_rn(v00, v01);
                *(__half2*)&C[(size_t)r1*ldc + cc] = __floats2half2_rn(v10, v11);
            } else {
                __half* C = (__half*)ha.C[z];
                C[(size_t)(cc  )*ldc + r0] = __float2half(v00);
                C[(size_t)(cc+1)*ldc + r0] = __float2half(v01);
                C[(size_t)(cc  )*ldc + r1] = __float2half(v10);
                C[(size_t)(cc+1)*ldc + r1] = __float2half(v11);
            }
        }
    }
}

// ---------------- softmax: warp per row of 256 ----------------
__global__ void softmax_kernel()
{
    int warp = threadIdx.x >> 5, lane = threadIdx.x & 31;
    size_t row = (size_t)blockIdx.x * 8 + warp;
    const float* rp = g_S + row * 256;
    float4 v0 = ((const float4*)rp)[lane*2];
    float4 v1 = ((const float4*)rp)[lane*2 + 1];
    float mx = fmaxf(fmaxf(fmaxf(v0.x, v0.y), fmaxf(v0.z, v0.w)),
                     fmaxf(fmaxf(v1.x, v1.y), fmaxf(v1.z, v1.w)));
    #pragma unroll
    for (int o = 16; o; o >>= 1) mx = fmaxf(mx, __shfl_xor_sync(0xffffffffu, mx, o));
    float e[8];
    e[0] = __expf(v0.x - mx); e[1] = __expf(v0.y - mx);
    e[2] = __expf(v0.z - mx); e[3] = __expf(v0.w - mx);
    e[4] = __expf(v1.x - mx); e[5] = __expf(v1.y - mx);
    e[6] = __expf(v1.z - mx); e[7] = __expf(v1.w - mx);
    float s = e[0]+e[1]+e[2]+e[3]+e[4]+e[5]+e[6]+e[7];
    #pragma unroll
    for (int o = 16; o; o >>= 1) s += __shfl_xor_sync(0xffffffffu, s, o);
    float inv = 1.0f / s;
    __half2 h0 = __floats2half2_rn(e[0]*inv, e[1]*inv);
    __half2 h1 = __floats2half2_rn(e[2]*inv, e[3]*inv);
    __half2 h2 = __floats2half2_rn(e[4]*inv, e[5]*inv);
    __half2 h3 = __floats2half2_rn(e[6]*inv, e[7]*inv);
    uint4 u = { *(uint32_t*)&h0, *(uint32_t*)&h1, *(uint32_t*)&h2, *(uint32_t*)&h3 };
    *(uint4*)(g_S16 + row * 256 + lane * 8) = u;
}

// ---------------- bfold (parallel) ----------------
__global__ void bfold_kernel(const float* __restrict__ wm,
                             const float* __restrict__ bz,
                             const float* __restrict__ bm)
{
    int r = blockIdx.x, t = threadIdx.x;
    float s = wm[(size_t)r*768 + t] * bz[t]
            + wm[(size_t)r*768 + 256 + t] * bz[256 + t];
    __shared__ float red[8];
    #pragma unroll
    for (int o = 16; o; o >>= 1) s += __shfl_xor_sync(0xffffffffu, s, o);
    if ((t & 31) == 0) red[t >> 5] = s;
    __syncthreads();
    if (t == 0) {
        float tot = bm[r];
        #pragma unroll
        for (int i = 0; i < 8; i++) tot += red[i];
        g_bf[r] = tot;
    }
}

// ======== fused v3: resident-A (192x256) fp16 mma + 4 y-rows/block =======
// SMEM (words): A [0,24576) stride 128 words/row, XOR swizzle (word ^ ((r&7)<<2)).
//               B bufs @24576 + buf*16512, 128 px rows, stride 129 (packed k-pairs).
// Grid (32, 4, 8): y0 = bx*4, m0 = by*64, b = bz. 512 threads, warps 4x4.
#define FUSED_SMEM 230400
#define A_WORDS 24576
#define B_WORDS 16512

__global__ void __launch_bounds__(512) fused_f16_gate(float* __restrict__ out)
{
    extern __shared__ uint32_t sm[];
    uint32_t* Asm = sm;
    int tid = threadIdx.x, lane = tid & 31, wid = tid >> 5;
    int y0 = blockIdx.x * 4;
    int m0 = blockIdx.y * 64;
    int b  = blockIdx.z;
    int wmi = wid >> 2, wni = wid & 3;
    int g = lane >> 2, tg = lane & 3;

    const __half* Xbase = g_h16 + (size_t)b * 256 * HW_;

    // ---- prologue: stage A (192 rows x 256 k = 32 uint4/row, swizzled) ----
    #pragma unroll
    for (int i = 0; i < 12; i++) {
        int slot = tid + 512*i;                 // 0..6143
        int r = slot >> 5, q32 = slot & 31;     // row 0..191, uint4 0..31
        int grow = (r >> 6) * 256 + m0 + (r & 63);
        uint4 v = *(const uint4*)(g_w16 + (size_t)grow*256 + q32*8);
        *(uint4*)&Asm[r*128 + 4*(q32 ^ (r & 7))] = v;
    }

    int kk = tid >> 4, px8 = tid & 15;          // B staging: kk 0..31, px8 0..15

    // ---- load + store B(0) ----
    {
        const __half* Xy = Xbase + (size_t)y0 * 128;
        uint32_t* Bv = sm + A_WORDS;
        #pragma unroll
        for (int i = 0; i < 4; i++) {
            int kp = i*32 + kk;
            uint4 lo = *(const uint4*)(Xy + (size_t)(2*kp  )*HW_ + px8*8);
            uint4 hi = *(const uint4*)(Xy + (size_t)(2*kp+1)*HW_ + px8*8);
            const unsigned short* lp = (const unsigned short*)&lo;
            const unsigned short* hp = (const unsigned short*)&hi;
            #pragma unroll
            for (int j = 0; j < 8; j++)
                Bv[(px8*8 + j)*129 + kp] = (uint32_t)lp[j] | ((uint32_t)hp[j] << 16);
        }
    }
    __syncthreads();

    const size_t OUT2 = (size_t)B_ * 256 * HW_;

    for (int yi = 0; yi < 4; yi++) {
        int y = y0 + yi;
        uint32_t* Bcur = sm + A_WORDS + (yi & 1) * B_WORDS;

        // prefetch B(y+1)
        uint4 pl[4], ph[4];
        if (yi < 3) {
            const __half* Xy = Xbase + (size_t)(y+1) * 128;
            #pragma unroll
            for (int i = 0; i < 4; i++) {
                int kp = i*32 + kk;
                pl[i] = *(const uint4*)(Xy + (size_t)(2*kp  )*HW_ + px8*8);
                ph[i] = *(const uint4*)(Xy + (size_t)(2*kp+1)*HW_ + px8*8);
            }
        }

        // ---- mma: 8 k-chunks, no barriers ----
        float acc[3][4][4];
        #pragma unroll
        for (int s = 0; s < 3; s++)
            #pragma unroll
            for (int n = 0; n < 4; n++)
                #pragma unroll
                for (int c = 0; c < 4; c++) acc[s][n][c] = 0.0f;

        for (int kc = 0; kc < 8; kc++) {
            #pragma unroll
            for (int ks = 0; ks < 2; ks++) {
                int kp0 = kc*16 + ks*8 + tg;
                uint32_t bfr[4][2];
                #pragma unroll
                for (int nt = 0; nt < 4; nt++) {
                    int n = wni*32 + nt*8 + g;
                    bfr[nt][0] = Bcur[n*129 + kp0];
                    bfr[nt][1] = Bcur[n*129 + kp0 + 4];
                }
                int sw0 = kp0 ^ (g << 2);
                int sw4 = sw0 ^ 4;
                #pragma unroll
                for (int s = 0; s < 3; s++) {
                    int rb = s*64 + wmi*16;
                    uint32_t a0 = Asm[(rb + g    )*128 + sw0];
                    uint32_t a1 = Asm[(rb + 8 + g)*128 + sw0];
                    uint32_t a2 = Asm[(rb + g    )*128 + sw4];
                    uint32_t a3 = Asm[(rb + 8 + g)*128 + sw4];
                    #pragma unroll
                    for (int nt = 0; nt < 4; nt++)
                        asm volatile(
                            "mma.sync.aligned.m16n8k16.row.col.f32.f16.f16.f32 "
                            "{%0,%1,%2,%3},{%4,%5,%6,%7},{%8,%9},{%0,%1,%2,%3};\n"
                            : "+f"(acc[s][nt][0]), "+f"(acc[s][nt][1]),
                              "+f"(acc[s][nt][2]), "+f"(acc[s][nt][3])
                            : "r"(a0), "r"(a1), "r"(a2), "r"(a3),
                              "r"(bfr[nt][0]), "r"(bfr[nt][1]));
                }
            }
        }
        __syncthreads();   // mma done reading Bcur; prior epilogue reads done

        // store B(y+1) into other buffer
        if (yi < 3) {
            uint32_t* Bnx = sm + A_WORDS + ((yi+1) & 1) * B_WORDS;
            #pragma unroll
            for (int i = 0; i < 4; i++) {
                int kp = i*32 + kk;
                const unsigned short* lp = (const unsigned short*)&pl[i];
                const unsigned short* hp = (const unsigned short*)&ph[i];
                #pragma unroll
                for (int j = 0; j < 8; j++)
                    Bnx[(px8*8 + j)*129 + kp] = (uint32_t)lp[j] | ((uint32_t)hp[j] << 16);
            }
        }

        // stage gy(y) into retired Bcur (192 x 16 floats)
        float* gy = (float*)Bcur;
        {
            float sy = (y + 0.5f) * 0.125f - 0.5f; if (sy < 0.0f) sy = 0.0f;
            int yy0 = (int)sy; float fy = sy - (float)yy0; int yy1 = min(yy0 + 1, 15);
            #pragma unroll
            for (int i = 0; i < 6; i++) {
                int idx = tid + 512*i;
                int r = idx >> 4, px16 = idx & 15;
                int grow = (r >> 6) * 256 + m0 + (r & 63);
                const float* Gb = g_G + ((size_t)b*768 + grow) * 256;
                gy[r*16 + px16] = (1.0f - fy) * Gb[yy0*16 + px16] + fy * Gb[yy1*16 + px16];
            }
        }
        __syncthreads();

        // ---- gating epilogue ----
        #pragma unroll
        for (int rr = 0; rr < 2; rr++) {
            int o_loc  = wmi*16 + g + rr*8;
            int o_glob = m0 + o_loc;
            float bv0 = g_bf[o_glob];
            float bv1 = g_bf[256 + o_glob];
            float bv2 = g_bf[512 + o_glob];
            const __half* mrow = g_m16 + ((size_t)b*256 + o_glob)*HW_ + (size_t)y*128;
            float* hrow = out + ((size_t)b*256 + o_glob)*HW_ + (size_t)y*128;
            float* mrow_out = hrow + OUT2;
            #pragma unroll
            for (int nt = 0; nt < 4; nt++) {
                int x = wni*32 + nt*8 + tg*2;
                __half2 mh = *(const __half2*)&mrow[x];
                float2 mv = __half22float2(mh);
                float nh[2], nm[2];
                #pragma unroll
                for (int px = 0; px < 2; px++) {
                    int xx = x + px;
                    float sx = (xx + 0.5f) * 0.125f - 0.5f; if (sx < 0.0f) sx = 0.0f;
                    int x0 = (int)sx; float fx = sx - (float)x0; int x1 = min(x0 + 1, 15);
                    float g0 = (1.0f-fx)*gy[(0*64+o_loc)*16 + x0] + fx*gy[(0*64+o_loc)*16 + x1];
                    float g1 = (1.0f-fx)*gy[(1*64+o_loc)*16 + x0] + fx*gy[(1*64+o_loc)*16 + x1];
                    float g2 = (1.0f-fx)*gy[(2*64+o_loc)*16 + x0] + fx*gy[(2*64+o_loc)*16 + x1];
                    int cc = rr*2 + px;
                    float mo = acc[0][nt][cc] + bv0 + g0;
                    float mg = acc[1][nt][cc] + bv1 + g1;
                    float mi = acc[2][nt][cc] + bv2 + g2;
                    float mval = px ? mv.y : mv.x;
                    float gi = fast_sig(mi);
                    float nmv = (1.0f - gi) * mval + gi * fast_tanh(mg);
                    nm[px] = nmv;
                    nh[px] = nmv * fast_sig(mo);
                }
                *(float2*)&hrow[x]     = make_float2(nh[0], nh[1]);
                *(float2*)&mrow_out[x] = make_float2(nm[0], nm[1]);
            }
        }
        // no barrier needed here: next iteration's post-mma barrier orders
        // these gy reads before B(y+2) overwrites Bcur.
    }
}

// ---------------- launcher ----------------
extern "C" void kernel_launch(void* const* d_in, const int* in_sizes, int n_in,
                              void* d_out, int out_size)
{
    const float* h   = (const float*)d_in[0];
    const float* m   = (const float*)d_in[1];
    const float* wq  = (const float*)d_in[2];
    const float* bq  = (const float*)d_in[3];
    const float* wk  = (const float*)d_in[4];
    const float* bk  = (const float*)d_in[5];
    const float* wv  = (const float*)d_in[6];
    const float* bv  = (const float*)d_in[7];
    const float* wkm = (const float*)d_in[8];
    const float* bkm = (const float*)d_in[9];
    const float* wvm = (const float*)d_in[10];
    const float* bvm = (const float*)d_in[11];
    const float* wz  = (const float*)d_in[12];
    const float* bz  = (const float*)d_in[13];
    const float* wm  = (const float*)d_in[14];
    const float* bm  = (const float*)d_in[15];
    float* out = (float*)d_out;

    float *S, *G;
    __half *HpT, *MpT, *W516, *QT, *KT, *KmT, *V, *Vm, *S16, *ZTT, *Wzz16, *wzT16, *wma16;
    cudaGetSymbolAddress((void**)&S,     g_S);
    cudaGetSymbolAddress((void**)&S16,   g_S16);
    cudaGetSymbolAddress((void**)&ZTT,   g_ZTT);
    cudaGetSymbolAddress((void**)&G,     g_G);
    cudaGetSymbolAddress((void**)&Wzz16, g_Wzz16);
    cudaGetSymbolAddress((void**)&wzT16, g_wzT16);
    cudaGetSymbolAddress((void**)&wma16, g_wma16);
    cudaGetSymbolAddress((void**)&HpT,   g_HpT);
    cudaGetSymbolAddress((void**)&MpT,   g_MpT);
    cudaGetSymbolAddress((void**)&W516,  g_W516);
    cudaGetSymbolAddress((void**)&QT,    g_QT);
    cudaGetSymbolAddress((void**)&KT,    g_KT);
    cudaGetSymbolAddress((void**)&KmT,   g_KmT);
    cudaGetSymbolAddress((void**)&V,     g_V);
    cudaGetSymbolAddress((void**)&Vm,    g_Vm);

    cudaFuncSetAttribute(fused_f16_gate,
                         cudaFuncAttributeMaxDynamicSharedMemorySize, FUSED_SMEM);

    // 1) pooling + merged weight preps + bias fold
    pool_kernel<<<dim3(8192, 2), 256>>>(h, m);
    prep_all<<<1152, 1024>>>(wm, wq, wk, wv, wkm, wvm, wz);
    bfold_kernel<<<768, 256>>>(wm, bz, bm);

    // 2) Wzz fold (fp16 mma)
    {
        HArgs ha = {};
        ha.A[0] = wma16; ha.B[0] = wzT16; ha.C[0] = Wzz16;
        gemm_h<1,false><<<dim3(8,12,1), 256>>>(ha, 512, 512, 512, 512);
    }

    // 3a) projections with transposed fp16 output: Q^T, K^T, Km^T
    {
        HArgs ha = {};
        const __half* W3[3] = { W516 + 0*65536, W516 + 1*65536, W516 + 3*65536 };
        const float*  b3[3] = { bq, bk, bkm };
        __half* C3[3] = { QT, KT, KmT };
        for (int s = 0; s < 3; s++)
            for (int bt = 0; bt < 8; bt++) {
                int z = s*8 + bt;
                ha.A[z] = W3[s];
                ha.B[z] = (s < 2 ? HpT : MpT) + bt*PB;
                ha.C[z] = C3[s] + bt*PB;
                ha.bias[z] = b3[s];
            }
        gemm_h<2,true><<<dim3(4,4,24), 256>>>(ha, 256, 256, 256, 256);
    }
    // 3b) V, Vm
    {
        HArgs ha = {};
        const __half* W2[2] = { W516 + 2*65536, W516 + 4*65536 };
        const float*  b2[2] = { bv, bvm };
        __half* C2[2] = { V, Vm };
        for (int s = 0; s < 2; s++)
            for (int bt = 0; bt < 8; bt++) {
                int z = s*8 + bt;
                ha.A[z] = W2[s];
                ha.B[z] = (s == 0 ? HpT : MpT) + bt*PB;
                ha.C[z] = C2[s] + bt*PB;
                ha.bias[z] = b2[s];
            }
        gemm_h<1,true><<<dim3(4,4,16), 256>>>(ha, 256, 256, 256, 256);
    }

    // 4) scores
    {
        HArgs ha = {};
        for (int z = 0; z < 16; z++) {
            int bt = z & 7;
            ha.A[z] = QT + bt*PB;
            ha.B[z] = ((z < 8) ? KT : KmT) + bt*PB;
            ha.C[z] = S + (long long)z*PB;
        }
        gemm_h<0,false><<<dim3(4,4,16), 256>>>(ha, 256, 256, 256, 256);
    }

    // 5) softmax -> S16
    softmax_kernel<<<512, 256>>>();

    // 6) ZTT (transposed fp16 out, ldc=512)
    {
        HArgs ha = {};
        for (int z = 0; z < 16; z++) {
            int bt = z & 7;
            ha.A[z] = ((z < 8) ? V : Vm) + bt*PB;
            ha.B[z] = S16 + (long long)z*PB;
            ha.C[z] = ZTT + (long long)bt*256*512 + ((z < 8) ? 0 : 256);
        }
        gemm_h<2,false><<<dim3(4,4,16), 256>>>(ha, 256, 256, 512, 256);
    }

    // 7) G = Wzz16 . ZTT  (fp32 out, K=512)
    {
        HArgs ha = {};
        for (int bt = 0; bt < 8; bt++) {
            ha.A[bt] = Wzz16;
            ha.B[bt] = ZTT + (long long)bt*256*512;
            ha.C[bt] = G + (long long)bt*768*256;
        }
        gemm_h<0,false><<<dim3(4,12,8), 256>>>(ha, 512, 512, 256, 512);
    }

    // 8) fused v3
    fused_f16_gate<<<dim3(32, 4, 8), 512, FUSED_SMEM>>>(out);
}

// round 15
// speedup vs baseline: 1.7402x; 1.0134x over previous
#include <cuda_runtime.h>
#include <cuda_fp16.h>
#include <cstdint>

#define B_   8
#define HW_  16384
#define PB   (256LL*256LL)

// ---------------- scratch ----------------
__device__ float  g_S [2*B_*256*256];
__device__ __half g_S16[2*B_*256*256];
__device__ __half g_ZTT[B_*256*512];
__device__ float  g_G [B_*768*256];
__device__ __half g_Wzz16[768*512];
__device__ __half g_wzT16[512*512];
__device__ __half g_wma16[768*512];
__device__ float  g_bf[768];
__device__ __half g_h16[(size_t)B_*256*HW_];
__device__ __half g_m16[(size_t)B_*256*HW_];
__device__ __half g_w16[768*256];
__device__ __half g_W516[5*256*256];
__device__ __half g_HpT[B_*256*256];
__device__ __half g_MpT[B_*256*256];
__device__ __half g_QT [B_*256*256];
__device__ __half g_KT [B_*256*256];
__device__ __half g_KmT[B_*256*256];
__device__ __half g_V  [B_*256*256];
__device__ __half g_Vm [B_*256*256];

__device__ __forceinline__ float fast_tanh(float x) {
    float r; asm("tanh.approx.f32 %0, %1;" : "=f"(r) : "f"(x)); return r;
}
__device__ __forceinline__ float fast_sig(float x) {
    return 1.0f / (1.0f + __expf(-x));
}

// ---------------- pooling ----------------
__global__ void pool_kernel(const float* __restrict__ h, const float* __restrict__ m)
{
    int tid = threadIdx.x;
    int hw = tid >> 4, l16 = tid & 15;
    const float* src = blockIdx.y ? m : h;
    __half* d16  = blockIdx.y ? g_m16 : g_h16;
    __half* dstT = blockIdx.y ? g_MpT : g_HpT;
    int gh = blockIdx.x * 16 + hw;
    int s0 = gh * 4;

    float4 v[4];
    #pragma unroll
    for (int j = 0; j < 4; j++)
        v[j] = *(const float4*)(src + (size_t)(s0 + j) * 64 + l16 * 4);

    #pragma unroll
    for (int j = 0; j < 4; j++) {
        __half2 p0 = __floats2half2_rn(v[j].x, v[j].y);
        __half2 p1 = __floats2half2_rn(v[j].z, v[j].w);
        uint2 u;
        u.x = *(const uint32_t*)&p0;
        u.y = *(const uint32_t*)&p1;
        *(uint2*)(d16 + (size_t)(s0 + j) * 64 + l16 * 4) = u;
    }

    #pragma unroll
    for (int j = 0; j < 4; j++) {
        float s = v[j].x + v[j].y + v[j].z + v[j].w;
        #pragma unroll
        for (int o = 8; o; o >>= 1) s += __shfl_xor_sync(0xffffffffu, s, o);
        if (l16 == 0) {
            int idx = s0 + j;
            int off = (idx & 0xFF0000) | ((idx & 255) << 8) | ((idx >> 8) & 255);
            dstT[off] = __float2half(s * (1.0f / 64.0f));
        }
    }
}

// ---------------- merged fp16 weight prep ----------------
#define N1_ (768*256)
#define N2_ (5*65536)
#define N3_ (768*512)
#define N4_ (512*512)
__global__ void prep_all(const float* __restrict__ wm,
                         const float* __restrict__ w0, const float* __restrict__ w1,
                         const float* __restrict__ w2, const float* __restrict__ w3,
                         const float* __restrict__ w4,
                         const float* __restrict__ wz)
{
    int i = blockIdx.x * 1024 + threadIdx.x;
    if (i < N1_) {
        int r = i >> 8, k = i & 255;
        g_w16[i] = __float2half(wm[(size_t)r*768 + 512 + k]);
    } else if (i < N1_ + N2_) {
        int i2 = i - N1_;
        const float* w;
        switch (i2 >> 16) {
            case 0: w = w0; break;
            case 1: w = w1; break;
            case 2: w = w2; break;
            case 3: w = w3; break;
            default: w = w4; break;
        }
        g_W516[i2] = __float2half(w[i2 & 65535]);
    } else if (i < N1_ + N2_ + N3_) {
        int i3 = i - N1_ - N2_;
        int r = i3 >> 9, o = i3 & 511;
        g_wma16[i3] = __float2half(wm[(size_t)r*768 + o]);
    } else if (i < N1_ + N2_ + N3_ + N4_) {
        int i4 = i - N1_ - N2_ - N3_;
        int c = i4 >> 9, o = i4 & 511;
        g_wzT16[c*512 + o] = __float2half(wz[(size_t)o*512 + c]);
    }
}

// ------- unified batched fp16 mma GEMM: double-buffered, per-z geometry ---
// A [m][k], B [n][k] fp16; mode: 0=f32 [m][n], 1=f16 [m][n], 2=f16 [n][m].
#define ZMAX 41
struct HU {
    const __half* A[ZMAX];
    const __half* B[ZMAX];
    void*         C[ZMAX];
    const float*  bias[ZMAX];
    int lda[ZMAX], ldb[ZMAX], ldc[ZMAX], K[ZMAX];
    unsigned char mode[ZMAX], mb[ZMAX], nb[ZMAX];
};

__global__ void __launch_bounds__(256) gemm_hu(HU hu)
{
    int z = blockIdx.z;
    if (blockIdx.y >= hu.mb[z] || blockIdx.x >= hu.nb[z]) return;

    __shared__ uint32_t As[2][64*12];
    __shared__ uint32_t Bs[2][64*12];
    int tid = threadIdx.x;
    const __half* Ab = hu.A[z];
    const __half* Bb = hu.B[z];
    int lda = hu.lda[z], ldb = hu.ldb[z], ldc = hu.ldc[z];
    int nk = hu.K[z] >> 4;
    int m0 = blockIdx.y * 64, n0 = blockIdx.x * 64;
    int lane = tid & 31, wid = tid >> 5;
    int wmi = wid >> 2, wni = wid & 3;
    int g = lane >> 2, tg = lane & 3;
    float acc[2][2][4] = {};
    int srow = tid >> 2, sq = tid & 3;

    uint2 av = *(const uint2*)(Ab + (size_t)(m0+srow)*lda + sq*4);
    uint2 bv = *(const uint2*)(Bb + (size_t)(n0+srow)*ldb + sq*4);
    *(uint2*)&As[0][srow*12 + sq*2] = av;
    *(uint2*)&Bs[0][srow*12 + sq*2] = bv;
    __syncthreads();

    for (int kt = 0; kt < nk; kt++) {
        uint2 av2, bv2;
        if (kt + 1 < nk) {
            int k0 = (kt + 1) << 4;
            av2 = *(const uint2*)(Ab + (size_t)(m0+srow)*lda + k0 + sq*4);
            bv2 = *(const uint2*)(Bb + (size_t)(n0+srow)*ldb + k0 + sq*4);
        }
        int cur = kt & 1;
        uint32_t bf[2][2];
        #pragma unroll
        for (int nt = 0; nt < 2; nt++) {
            int nr = wni*16 + nt*8 + g;
            bf[nt][0] = Bs[cur][nr*12 + tg];
            bf[nt][1] = Bs[cur][nr*12 + 4 + tg];
        }
        #pragma unroll
        for (int mt = 0; mt < 2; mt++) {
            int rb = wmi*32 + mt*16;
            uint32_t a0 = As[cur][(rb + g    )*12 + tg];
            uint32_t a1 = As[cur][(rb + 8 + g)*12 + tg];
            uint32_t a2 = As[cur][(rb + g    )*12 + 4 + tg];
            uint32_t a3 = As[cur][(rb + 8 + g)*12 + 4 + tg];
            #pragma unroll
            for (int nt = 0; nt < 2; nt++)
                asm volatile(
                    "mma.sync.aligned.m16n8k16.row.col.f32.f16.f16.f32 "
                    "{%0,%1,%2,%3},{%4,%5,%6,%7},{%8,%9},{%0,%1,%2,%3};\n"
                    : "+f"(acc[mt][nt][0]), "+f"(acc[mt][nt][1]),
                      "+f"(acc[mt][nt][2]), "+f"(acc[mt][nt][3])
                    : "r"(a0), "r"(a1), "r"(a2), "r"(a3),
                      "r"(bf[nt][0]), "r"(bf[nt][1]));
        }
        if (kt + 1 < nk) {
            int nxt = (kt + 1) & 1;
            *(uint2*)&As[nxt][srow*12 + sq*2] = av2;
            *(uint2*)&Bs[nxt][srow*12 + sq*2] = bv2;
            __syncthreads();
        }
    }

    int mode = hu.mode[z];
    const float* bias = hu.bias[z];
    #pragma unroll
    for (int mt = 0; mt < 2; mt++) {
        int r0 = m0 + wmi*32 + mt*16 + g;
        int r1 = r0 + 8;
        float bv0 = bias ? bias[r0] : 0.0f;
        float bv1 = bias ? bias[r1] : 0.0f;
        #pragma unroll
        for (int nt = 0; nt < 2; nt++) {
            int cc = n0 + wni*16 + nt*8 + tg*2;
            float v00 = acc[mt][nt][0] + bv0, v01 = acc[mt][nt][1] + bv0;
            float v10 = acc[mt][nt][2] + bv1, v11 = acc[mt][nt][3] + bv1;
            if (mode == 0) {
                float* C = (float*)hu.C[z];
                *(float2*)&C[(size_t)r0*ldc + cc] = make_float2(v00, v01);
                *(float2*)&C[(size_t)r1*ldc + cc] = make_float2(v10, v11);
            } else if (mode == 1) {
                __half* C = (__half*)hu.C[z];
                *(__half2*)&C[(size_t)r0*ldc + cc] = __floats2half2_rn(v00, v01);
                *(__half2*)&C[(size_t)r1*ldc + cc] = __floats2half2_rn(v10, v11);
            } else {
                __half* C = (__half*)hu.C[z];
                C[(size_t)(cc  )*ldc + r0] = __float2half(v00);
                C[(size_t)(cc+1)*ldc + r0] = __float2half(v01);
                C[(size_t)(cc  )*ldc + r1] = __float2half(v10);
                C[(size_t)(cc+1)*ldc + r1] = __float2half(v11);
            }
        }
    }
}

// ---------------- softmax: warp per row of 256 ----------------
__global__ void softmax_kernel()
{
    int warp = threadIdx.x >> 5, lane = threadIdx.x & 31;
    size_t row = (size_t)blockIdx.x * 8 + warp;
    const float* rp = g_S + row * 256;
    float4 v0 = ((const float4*)rp)[lane*2];
    float4 v1 = ((const float4*)rp)[lane*2 + 1];
    float mx = fmaxf(fmaxf(fmaxf(v0.x, v0.y), fmaxf(v0.z, v0.w)),
                     fmaxf(fmaxf(v1.x, v1.y), fmaxf(v1.z, v1.w)));
    #pragma unroll
    for (int o = 16; o; o >>= 1) mx = fmaxf(mx, __shfl_xor_sync(0xffffffffu, mx, o));
    float e[8];
    e[0] = __expf(v0.x - mx); e[1] = __expf(v0.y - mx);
    e[2] = __expf(v0.z - mx); e[3] = __expf(v0.w - mx);
    e[4] = __expf(v1.x - mx); e[5] = __expf(v1.y - mx);
    e[6] = __expf(v1.z - mx); e[7] = __expf(v1.w - mx);
    float s = e[0]+e[1]+e[2]+e[3]+e[4]+e[5]+e[6]+e[7];
    #pragma unroll
    for (int o = 16; o; o >>= 1) s += __shfl_xor_sync(0xffffffffu, s, o);
    float inv = 1.0f / s;
    __half2 h0 = __floats2half2_rn(e[0]*inv, e[1]*inv);
    __half2 h1 = __floats2half2_rn(e[2]*inv, e[3]*inv);
    __half2 h2 = __floats2half2_rn(e[4]*inv, e[5]*inv);
    __half2 h3 = __floats2half2_rn(e[6]*inv, e[7]*inv);
    uint4 u = { *(uint32_t*)&h0, *(uint32_t*)&h1, *(uint32_t*)&h2, *(uint32_t*)&h3 };
    *(uint4*)(g_S16 + row * 256 + lane * 8) = u;
}

// ---------------- bfold ----------------
__global__ void bfold_kernel(const float* __restrict__ wm,
                             const float* __restrict__ bz,
                             const float* __restrict__ bm)
{
    int r = blockIdx.x, t = threadIdx.x;
    float s = wm[(size_t)r*768 + t] * bz[t]
            + wm[(size_t)r*768 + 256 + t] * bz[256 + t];
    __shared__ float red[8];
    #pragma unroll
    for (int o = 16; o; o >>= 1) s += __shfl_xor_sync(0xffffffffu, s, o);
    if ((t & 31) == 0) red[t >> 5] = s;
    __syncthreads();
    if (t == 0) {
        float tot = bm[r];
        #pragma unroll
        for (int i = 0; i < 8; i++) tot += red[i];
        g_bf[r] = tot;
    }
}

// ======== fused v3: resident-A (192x256) fp16 mma + 4 y-rows/block =======
#define FUSED_SMEM 230400
#define A_WORDS 24576
#define B_WORDS 16512

__global__ void __launch_bounds__(512) fused_f16_gate(float* __restrict__ out)
{
    extern __shared__ uint32_t sm[];
    uint32_t* Asm = sm;
    int tid = threadIdx.x, lane = tid & 31, wid = tid >> 5;
    int y0 = blockIdx.x * 4;
    int m0 = blockIdx.y * 64;
    int b  = blockIdx.z;
    int wmi = wid >> 2, wni = wid & 3;
    int g = lane >> 2, tg = lane & 3;

    const __half* Xbase = g_h16 + (size_t)b * 256 * HW_;

    #pragma unroll
    for (int i = 0; i < 12; i++) {
        int slot = tid + 512*i;
        int r = slot >> 5, q32 = slot & 31;
        int grow = (r >> 6) * 256 + m0 + (r & 63);
        uint4 v = *(const uint4*)(g_w16 + (size_t)grow*256 + q32*8);
        *(uint4*)&Asm[r*128 + 4*(q32 ^ (r & 7))] = v;
    }

    int kk = tid >> 4, px8 = tid & 15;

    {
        const __half* Xy = Xbase + (size_t)y0 * 128;
        uint32_t* Bv = sm + A_WORDS;
        #pragma unroll
        for (int i = 0; i < 4; i++) {
            int kp = i*32 + kk;
            uint4 lo = *(const uint4*)(Xy + (size_t)(2*kp  )*HW_ + px8*8);
            uint4 hi = *(const uint4*)(Xy + (size_t)(2*kp+1)*HW_ + px8*8);
            const unsigned short* lp = (const unsigned short*)&lo;
            const unsigned short* hp = (const unsigned short*)&hi;
            #pragma unroll
            for (int j = 0; j < 8; j++)
                Bv[(px8*8 + j)*129 + kp] = (uint32_t)lp[j] | ((uint32_t)hp[j] << 16);
        }
    }
    __syncthreads();

    const size_t OUT2 = (size_t)B_ * 256 * HW_;

    for (int yi = 0; yi < 4; yi++) {
        int y = y0 + yi;
        uint32_t* Bcur = sm + A_WORDS + (yi & 1) * B_WORDS;

        uint4 pl[4], ph[4];
        if (yi < 3) {
            const __half* Xy = Xbase + (size_t)(y+1) * 128;
            #pragma unroll
            for (int i = 0; i < 4; i++) {
                int kp = i*32 + kk;
                pl[i] = *(const uint4*)(Xy + (size_t)(2*kp  )*HW_ + px8*8);
                ph[i] = *(const uint4*)(Xy + (size_t)(2*kp+1)*HW_ + px8*8);
            }
        }

        float acc[3][4][4];
        #pragma unroll
        for (int s = 0; s < 3; s++)
            #pragma unroll
            for (int n = 0; n < 4; n++)
                #pragma unroll
                for (int c = 0; c < 4; c++) acc[s][n][c] = 0.0f;

        for (int kc = 0; kc < 8; kc++) {
            #pragma unroll
            for (int ks = 0; ks < 2; ks++) {
                int kp0 = kc*16 + ks*8 + tg;
                uint32_t bfr[4][2];
                #pragma unroll
                for (int nt = 0; nt < 4; nt++) {
                    int n = wni*32 + nt*8 + g;
                    bfr[nt][0] = Bcur[n*129 + kp0];
                    bfr[nt][1] = Bcur[n*129 + kp0 + 4];
                }
                int sw0 = kp0 ^ (g << 2);
                int sw4 = sw0 ^ 4;
                #pragma unroll
                for (int s = 0; s < 3; s++) {
                    int rb = s*64 + wmi*16;
                    uint32_t a0 = Asm[(rb + g    )*128 + sw0];
                    uint32_t a1 = Asm[(rb + 8 + g)*128 + sw0];
                    uint32_t a2 = Asm[(rb + g    )*128 + sw4];
                    uint32_t a3 = Asm[(rb + 8 + g)*128 + sw4];
                    #pragma unroll
                    for (int nt = 0; nt < 4; nt++)
                        asm volatile(
                            "mma.sync.aligned.m16n8k16.row.col.f32.f16.f16.f32 "
                            "{%0,%1,%2,%3},{%4,%5,%6,%7},{%8,%9},{%0,%1,%2,%3};\n"
                            : "+f"(acc[s][nt][0]), "+f"(acc[s][nt][1]),
                              "+f"(acc[s][nt][2]), "+f"(acc[s][nt][3])
                            : "r"(a0), "r"(a1), "r"(a2), "r"(a3),
                              "r"(bfr[nt][0]), "r"(bfr[nt][1]));
                }
            }
        }
        __syncthreads();

        if (yi < 3) {
            uint32_t* Bnx = sm + A_WORDS + ((yi+1) & 1) * B_WORDS;
            #pragma unroll
            for (int i = 0; i < 4; i++) {
                int kp = i*32 + kk;
                const unsigned short* lp = (const unsigned short*)&pl[i];
                const unsigned short* hp = (const unsigned short*)&ph[i];
                #pragma unroll
                for (int j = 0; j < 8; j++)
                    Bnx[(px8*8 + j)*129 + kp] = (uint32_t)lp[j] | ((uint32_t)hp[j] << 16);
            }
        }

        float* gy = (float*)Bcur;
        {
            float sy = (y + 0.5f) * 0.125f - 0.5f; if (sy < 0.0f) sy = 0.0f;
            int yy0 = (int)sy; float fy = sy - (float)yy0; int yy1 = min(yy0 + 1, 15);
            #pragma unroll
            for (int i = 0; i < 6; i++) {
                int idx = tid + 512*i;
                int r = idx >> 4, px16 = idx & 15;
                int grow = (r >> 6) * 256 + m0 + (r & 63);
                const float* Gb = g_G + ((size_t)b*768 + grow) * 256;
                gy[r*16 + px16] = (1.0f - fy) * Gb[yy0*16 + px16] + fy * Gb[yy1*16 + px16];
            }
        }
        __syncthreads();

        #pragma unroll
        for (int rr = 0; rr < 2; rr++) {
            int o_loc  = wmi*16 + g + rr*8;
            int o_glob = m0 + o_loc;
            float bv0 = g_bf[o_glob];
            float bv1 = g_bf[256 + o_glob];
            float bv2 = g_bf[512 + o_glob];
            const __half* mrow = g_m16 + ((size_t)b*256 + o_glob)*HW_ + (size_t)y*128;
            float* hrow = out + ((size_t)b*256 + o_glob)*HW_ + (size_t)y*128;
            float* mrow_out = hrow + OUT2;
            #pragma unroll
            for (int nt = 0; nt < 4; nt++) {
                int x = wni*32 + nt*8 + tg*2;
                __half2 mh = *(const __half2*)&mrow[x];
                float2 mv = __half22float2(mh);
                float nh[2], nm[2];
                #pragma unroll
                for (int px = 0; px < 2; px++) {
                    int xx = x + px;
                    float sx = (xx + 0.5f) * 0.125f - 0.5f; if (sx < 0.0f) sx = 0.0f;
                    int x0 = (int)sx; float fx = sx - (float)x0; int x1 = min(x0 + 1, 15);
                    float g0 = (1.0f-fx)*gy[(0*64+o_loc)*16 + x0] + fx*gy[(0*64+o_loc)*16 + x1];
                    float g1 = (1.0f-fx)*gy[(1*64+o_loc)*16 + x0] + fx*gy[(1*64+o_loc)*16 + x1];
                    float g2 = (1.0f-fx)*gy[(2*64+o_loc)*16 + x0] + fx*gy[(2*64+o_loc)*16 + x1];
                    int cc = rr*2 + px;
                    float mo = acc[0][nt][cc] + bv0 + g0;
                    float mg = acc[1][nt][cc] + bv1 + g1;
                    float mi = acc[2][nt][cc] + bv2 + g2;
                    float mval = px ? mv.y : mv.x;
                    float gi = fast_sig(mi);
                    float nmv = (1.0f - gi) * mval + gi * fast_tanh(mg);
                    nm[px] = nmv;
                    nh[px] = nmv * fast_sig(mo);
                }
                *(float2*)&hrow[x]     = make_float2(nh[0], nh[1]);
                *(float2*)&mrow_out[x] = make_float2(nm[0], nm[1]);
            }
        }
    }
}

// ---------------- launcher ----------------
extern "C" void kernel_launch(void* const* d_in, const int* in_sizes, int n_in,
                              void* d_out, int out_size)
{
    const float* h   = (const float*)d_in[0];
    const float* m   = (const float*)d_in[1];
    const float* wq  = (const float*)d_in[2];
    const float* bq  = (const float*)d_in[3];
    const float* wk  = (const float*)d_in[4];
    const float* bk  = (const float*)d_in[5];
    const float* wv  = (const float*)d_in[6];
    const float* bv  = (const float*)d_in[7];
    const float* wkm = (const float*)d_in[8];
    const float* bkm = (const float*)d_in[9];
    const float* wvm = (const float*)d_in[10];
    const float* bvm = (const float*)d_in[11];
    const float* wz  = (const float*)d_in[12];
    const float* bz  = (const float*)d_in[13];
    const float* wm  = (const float*)d_in[14];
    const float* bm  = (const float*)d_in[15];
    float* out = (float*)d_out;

    float *S, *G;
    __half *HpT, *MpT, *W516, *QT, *KT, *KmT, *V, *Vm, *S16, *ZTT, *Wzz16, *wzT16, *wma16;
    cudaGetSymbolAddress((void**)&S,     g_S);
    cudaGetSymbolAddress((void**)&S16,   g_S16);
    cudaGetSymbolAddress((void**)&ZTT,   g_ZTT);
    cudaGetSymbolAddress((void**)&G,     g_G);
    cudaGetSymbolAddress((void**)&Wzz16, g_Wzz16);
    cudaGetSymbolAddress((void**)&wzT16, g_wzT16);
    cudaGetSymbolAddress((void**)&wma16, g_wma16);
    cudaGetSymbolAddress((void**)&HpT,   g_HpT);
    cudaGetSymbolAddress((void**)&MpT,   g_MpT);
    cudaGetSymbolAddress((void**)&W516,  g_W516);
    cudaGetSymbolAddress((void**)&QT,    g_QT);
    cudaGetSymbolAddress((void**)&KT,    g_KT);
    cudaGetSymbolAddress((void**)&KmT,   g_KmT);
    cudaGetSymbolAddress((void**)&V,     g_V);
    cudaGetSymbolAddress((void**)&Vm,    g_Vm);

    cudaFuncSetAttribute(fused_f16_gate,
                         cudaFuncAttributeMaxDynamicSharedMemorySize, FUSED_SMEM);

    // 1) pooling + prep + bias fold
    pool_kernel<<<dim3(8192, 2), 256>>>(h, m);
    prep_all<<<1152, 1024>>>(wm, wq, wk, wv, wkm, wvm, wz);
    bfold_kernel<<<768, 256>>>(wm, bz, bm);

    // 2) merged: Wzz fold (z=0) + all 5 projections (z=1..40)
    {
        HU hu = {};
        // z0: Wzz fold
        hu.A[0] = wma16; hu.B[0] = wzT16; hu.C[0] = Wzz16; hu.bias[0] = nullptr;
        hu.lda[0] = 512; hu.ldb[0] = 512; hu.ldc[0] = 512; hu.K[0] = 512;
        hu.mode[0] = 1; hu.mb[0] = 12; hu.nb[0] = 8;
        // z1..24: QT/KT/KmT (transposed out), z25..40: V/Vm
        const __half* W5[5] = { W516 + 0*65536, W516 + 1*65536, W516 + 3*65536,
                                W516 + 2*65536, W516 + 4*65536 };   // wq,wk,wkm,wv,wvm
        const float*  b5[5] = { bq, bk, bkm, bv, bvm };
        __half* C5[5] = { QT, KT, KmT, V, Vm };
        const __half* in5[5] = { HpT, HpT, MpT, HpT, MpT };
        for (int s = 0; s < 5; s++)
            for (int bt = 0; bt < 8; bt++) {
                int z = 1 + s*8 + bt;
                hu.A[z] = W5[s];
                hu.B[z] = in5[s] + bt*PB;
                hu.C[z] = C5[s] + bt*PB;
                hu.bias[z] = b5[s];
                hu.lda[z] = 256; hu.ldb[z] = 256; hu.ldc[z] = 256; hu.K[z] = 256;
                hu.mode[z] = (s < 3) ? 2 : 1;
                hu.mb[z] = 4; hu.nb[z] = 4;
            }
        gemm_hu<<<dim3(8, 12, 41), 256>>>(hu);
    }

    // 3) scores (fp32 out)
    {
        HU hu = {};
        for (int z = 0; z < 16; z++) {
            int bt = z & 7;
            hu.A[z] = QT + bt*PB;
            hu.B[z] = ((z < 8) ? KT : KmT) + bt*PB;
            hu.C[z] = S + (long long)z*PB;
            hu.bias[z] = nullptr;
            hu.lda[z] = 256; hu.ldb[z] = 256; hu.ldc[z] = 256; hu.K[z] = 256;
            hu.mode[z] = 0; hu.mb[z] = 4; hu.nb[z] = 4;
        }
        gemm_hu<<<dim3(4, 4, 16), 256>>>(hu);
    }

    // 4) softmax -> S16
    softmax_kernel<<<512, 256>>>();

    // 5) ZTT (transposed fp16 out, ldc=512)
    {
        HU hu = {};
        for (int z = 0; z < 16; z++) {
            int bt = z & 7;
            hu.A[z] = ((z < 8) ? V : Vm) + bt*PB;
            hu.B[z] = S16 + (long long)z*PB;
            hu.C[z] = ZTT + (long long)bt*256*512 + ((z < 8) ? 0 : 256);
            hu.bias[z] = nullptr;
            hu.lda[z] = 256; hu.ldb[z] = 256; hu.ldc[z] = 512; hu.K[z] = 256;
            hu.mode[z] = 2; hu.mb[z] = 4; hu.nb[z] = 4;
        }
        gemm_hu<<<dim3(4, 4, 16), 256>>>(hu);
    }

    // 6) G = Wzz16 . ZTT  (fp32 out, K=512)
    {
        HU hu = {};
        for (int bt = 0; bt < 8; bt++) {
            hu.A[bt] = Wzz16;
            hu.B[bt] = ZTT + (long long)bt*256*512;
            hu.C[bt] = G + (long long)bt*768*256;
            hu.bias[bt] = nullptr;
            hu.lda[bt] = 512; hu.ldb[bt] = 512; hu.ldc[bt] = 256; hu.K[bt] = 512;
            hu.mode[bt] = 0; hu.mb[bt] = 12; hu.nb[bt] = 4;
        }
        gemm_hu<<<dim3(4, 12, 8), 256>>>(hu);
    }

    // 7) fused v3
    fused_f16_gate<<<dim3(32, 4, 8), 512, FUSED_SMEM>>>(out);
}